// round 10
// baseline (speedup 1.0000x reference)
#include <cuda_runtime.h>
#include <cuda_fp16.h>
#include <cstdint>
#include <math.h>

#define BB 4
#define TQ 1024
#define TKV 2048
#define DD 1024
#define HH 16
#define DHD 64

// ---------------- device scratch (static; no allocations) -------------------
__device__ __half g_x[BB*TQ*DD];                     // x fp16
__device__ __half g_Wq[DD*DD], g_Wk[DD*DD], g_Wv[DD*DD], g_Wo[DD*DD];
__device__ __half g_qhf[BB*TQ*DD];                   // [b,h,tq,64], x0.125
__device__ __half g_khf[BB*TKV*DD];                  // [b,h,kv,64]
__device__ __half g_vt[BB*TKV*DD];                   // [b,h,64,kv] transposed
__device__ __half g_av[BB*TQ*DD];                    // attn out fp16 [m,1024]

// ---------------- helpers ---------------------------------------------------
__device__ __forceinline__ uint32_t smem_u32(const void* p){
    uint32_t a;
    asm("{ .reg .u64 t; cvta.to.shared.u64 t, %1; cvt.u32.u64 %0, t; }" : "=r"(a) : "l"(p));
    return a;
}
#define SW128(o) ((o) ^ (((o) >> 3) & 0x70))

__device__ __forceinline__ void ldm4(uint32_t* r, uint32_t addr){
    asm volatile("ldmatrix.sync.aligned.m8n8.x4.shared.b16 {%0,%1,%2,%3}, [%4];"
        : "=r"(r[0]), "=r"(r[1]), "=r"(r[2]), "=r"(r[3]) : "r"(addr));
}
__device__ __forceinline__ void mma_f16(float* c, const uint32_t* a, uint32_t b0, uint32_t b1){
    asm volatile("mma.sync.aligned.m16n8k16.row.col.f32.f16.f16.f32 "
        "{%0,%1,%2,%3}, {%4,%5,%6,%7}, {%8,%9}, {%0,%1,%2,%3};"
        : "+f"(c[0]), "+f"(c[1]), "+f"(c[2]), "+f"(c[3])
        : "r"(a[0]), "r"(a[1]), "r"(a[2]), "r"(a[3]), "r"(b0), "r"(b1));
}
__device__ __forceinline__ void cp16(uint32_t dst, const void* src){
    asm volatile("cp.async.cg.shared.global [%0], [%1], 16;" :: "r"(dst), "l"(src));
}
#define CP_COMMIT() asm volatile("cp.async.commit_group;")
__device__ __forceinline__ void sts32(uint32_t addr, uint32_t v){
    asm volatile("st.shared.b32 [%0], %1;" :: "r"(addr), "r"(v));
}
__device__ __forceinline__ uint32_t h2u(__half2 v){
    return *reinterpret_cast<uint32_t*>(&v);
}

// ---------------- small prep kernels ---------------------------------------
// old cache rows -> output caches; ALSO emit K fp16 head-major operands
__global__ void copy_old_cache(const float4* __restrict__ ksrc,
                               const float4* __restrict__ vsrc,
                               float4* __restrict__ kdst,
                               float4* __restrict__ vdst){
    int i = blockIdx.x * blockDim.x + threadIdx.x;
    const int per_b = TQ * DD / 4;
    if (i >= BB * per_b) return;
    int b = i / per_b;
    int rem = i - b * per_b;
    size_t idx = (size_t)b * (TKV * DD / 4) + rem;
    float4 kv4 = ksrc[idx];
    kdst[idx] = kv4;
    vdst[idx] = vsrc[idx];
    int t = rem >> 8;
    int d = (rem & 255) * 4;
    int h = d >> 6, dh = d & 63;
    size_t o = (((size_t)b*HH + h)*TKV + t)*64 + dh;
    *(__half2*)(g_khf + o)     = __floats2half2_rn(kv4.x, kv4.y);
    *(__half2*)(g_khf + o + 2) = __floats2half2_rn(kv4.z, kv4.w);
}

// x fp32 -> fp16
__global__ void conv_x(const float4* __restrict__ src, int n4){
    int i = blockIdx.x * blockDim.x + threadIdx.x;
    if (i >= n4) return;
    float4 v = src[i];
    ((__half2*)g_x)[i*2+0] = __floats2half2_rn(v.x, v.y);
    ((__half2*)g_x)[i*2+1] = __floats2half2_rn(v.z, v.w);
}

// all 4 weights fp32 -> fp16 in one launch (blockIdx.y selects)
__global__ void conv_w4(const float4* __restrict__ Wq, const float4* __restrict__ Wk,
                        const float4* __restrict__ Wv, const float4* __restrict__ Wo,
                        int n4){
    int i = blockIdx.x * blockDim.x + threadIdx.x;
    if (i >= n4) return;
    const float4* src;
    __half* W;
    switch (blockIdx.y){
        case 0: src = Wq; W = g_Wq; break;
        case 1: src = Wk; W = g_Wk; break;
        case 2: src = Wv; W = g_Wv; break;
        default:src = Wo; W = g_Wo; break;
    }
    float4 v = src[i];
    ((__half2*)W)[i*2+0] = __floats2half2_rn(v.x, v.y);
    ((__half2*)W)[i*2+1] = __floats2half2_rn(v.z, v.w);
}

// V cache [b,kv,D] fp32 -> transposed fp16 [b,h,64,kv]
__global__ void vconv(const float* __restrict__ vc){
    __shared__ float t[128][65];
    int kv0 = blockIdx.x * 128, h = blockIdx.y, b = blockIdx.z;
    int tid = threadIdx.x;
    for (int i = tid; i < 128*16; i += 256){
        int r = i >> 4, c4 = i & 15;
        float4 v = *(const float4*)(vc + ((size_t)(b*TKV + kv0 + r))*DD + h*64 + c4*4);
        t[r][c4*4+0] = v.x; t[r][c4*4+1] = v.y; t[r][c4*4+2] = v.z; t[r][c4*4+3] = v.w;
    }
    __syncthreads();
    for (int i = tid; i < 64*128; i += 256){
        int dh = i >> 7, j = i & 127;
        size_t o = (((size_t)b*HH + h)*64 + dh)*TKV + kv0 + j;
        g_vt[o] = __float2half_rn(t[j][dh]);
    }
}

// ---------------- fp16 1-pass projection GEMM -------------------------------
// C[m,n] = sum_k A[m,k]*W[n,k] (+bias). 128x128 block, BK=64, double buffer.
// smem: 2 stages x {A 16K, W 16K} = 65536
#define G_STAGE 32768
#define G_SMEM  65536

__global__ void __launch_bounds__(256, 1) gemm_tc(int mode_base,
    const float* __restrict__ bq, const float* __restrict__ bvv, const float* __restrict__ bo,
    float* __restrict__ kout, float* __restrict__ vout, float* __restrict__ outp){
    extern __shared__ char sm[];
    const int mode = mode_base + blockIdx.z;
    const __half *A, *W;
    const float* bias;
    if (mode == 0)      { A=g_x;  W=g_Wq; bias=bq;  }
    else if (mode == 1) { A=g_x;  W=g_Wk; bias=0;   }
    else if (mode == 2) { A=g_x;  W=g_Wv; bias=bvv; }
    else                { A=g_av; W=g_Wo; bias=bo;  }

    uint32_t sb = smem_u32(sm);
    const int tid = threadIdx.x, wid = tid >> 5, lane = tid & 31;
    const int m0 = blockIdx.y * 128, n0 = blockIdx.x * 128;
    const int R0 = wid * 16;

    const __half* srcs[2] = { A + (size_t)m0*DD, W + (size_t)n0*DD };
    const int lr = tid >> 3, lkc = tid & 7;

#define G_ISSUE(ch, buf) do { \
    int k0_ = (ch) * 64; \
    _Pragma("unroll") \
    for (int t2 = 0; t2 < 2; t2++){ \
        uint32_t base_ = sb + (buf)*G_STAGE + t2*16384; \
        _Pragma("unroll") \
        for (int i_ = 0; i_ < 4; i_++){ \
            int r_ = lr + i_*32; \
            cp16(base_ + SW128((uint32_t)(r_*128 + lkc*16)), \
                 srcs[t2] + (size_t)r_*DD + k0_ + lkc*8); \
        } \
    } \
    CP_COMMIT(); \
} while (0)

    G_ISSUE(0, 0);
    G_ISSUE(1, 1);

    float acc[16][4];
#pragma unroll
    for (int i = 0; i < 16; i++)
#pragma unroll
        for (int j = 0; j < 4; j++) acc[i][j] = 0.f;

    const int ar  = R0 + (lane & 15);
    const int akh = lane >> 4;
    const int bi  = lane & 7;
    const int grp = lane >> 3;

    for (int ch = 0; ch < 16; ch++){
        if (ch == 15) asm volatile("cp.async.wait_group 0;" ::: "memory");
        else          asm volatile("cp.async.wait_group 1;" ::: "memory");
        __syncthreads();
        uint32_t ba = sb + (ch & 1) * G_STAGE;
#pragma unroll
        for (int k16 = 0; k16 < 4; k16++){
            uint32_t aoff = SW128((uint32_t)(ar*128 + (k16*2 + akh)*16));
            uint32_t a[4];
            ldm4(a, ba + aoff);
#pragma unroll
            for (int np = 0; np < 8; np++){
                int bn  = np*16 + (grp >> 1)*8 + bi;
                int bkc = k16*2 + (grp & 1);
                uint32_t boff = SW128((uint32_t)(bn*128 + bkc*16));
                uint32_t w[4];
                ldm4(w, ba + 16384 + boff);
                mma_f16(acc[np*2],   a, w[0], w[1]);
                mma_f16(acc[np*2+1], a, w[2], w[3]);
            }
        }
        __syncthreads();
        if (ch + 2 < 16) G_ISSUE(ch + 2, ch & 1);
    }
#undef G_ISSUE

    // epilogue
    const int r1 = m0 + R0 + (lane >> 2), r2 = r1 + 8;
#pragma unroll
    for (int nf = 0; nf < 16; nf++){
        int c = n0 + nf*8 + (lane & 3)*2;
        float v0 = acc[nf][0], v1 = acc[nf][1], v2 = acc[nf][2], v3 = acc[nf][3];
        if (bias){
            float2 bb = *(const float2*)(bias + c);
            v0 += bb.x; v1 += bb.y; v2 += bb.x; v3 += bb.y;
        }
        if (mode == 0){
            v0 *= 0.125f; v1 *= 0.125f; v2 *= 0.125f; v3 *= 0.125f;
            int h = c >> 6, dh = c & 63;
#pragma unroll
            for (int rr = 0; rr < 2; rr++){
                int row = rr ? r2 : r1;
                float a = rr ? v2 : v0, b2 = rr ? v3 : v1;
                int b = row >> 10, q = row & 1023;
                size_t o = (((size_t)b*HH + h)*TQ + q)*64 + dh;
                *(__half2*)(g_qhf + o) = __floats2half2_rn(a, b2);
            }
        } else if (mode == 3){
            *(float2*)(outp + (size_t)r1*DD + c) = make_float2(v0, v1);
            *(float2*)(outp + (size_t)r2*DD + c) = make_float2(v2, v3);
        } else {
            float* dst = (mode == 1) ? kout : vout;
            int h = c >> 6, dh = c & 63;
#pragma unroll
            for (int rr = 0; rr < 2; rr++){
                int row = rr ? r2 : r1;
                float a = rr ? v2 : v0, b2 = rr ? v3 : v1;
                int b = row >> 10, q = row & 1023;
                size_t o = ((size_t)b*TKV + TQ + q)*DD + c;
                *(float2*)(dst + o) = make_float2(a, b2);
                if (mode == 1){
                    size_t ko = (((size_t)b*HH + h)*TKV + TQ + q)*64 + dh;
                    *(__half2*)(g_khf + ko) = __floats2half2_rn(a, b2);
                }
            }
        }
    }
}

// ---------------- attention (fp16 1-pass S, 1-pass PV) ----------------------
// smem: Q 16K | P 32K | 3 stages x 32K {K fp16, V fp16}
#define A_QH 0
#define A_PH 16384
#define A_ST 49152
#define A_STAGE 32768
#define A_SMEM (49152 + 3*32768)     // 147456 (144KB)

__global__ void __launch_bounds__(256, 1) attn_tc(const float* __restrict__ mask){
    extern __shared__ char sm[];
    uint32_t sb = smem_u32(sm);
    const int tid = threadIdx.x, wid = tid >> 5, lane = tid & 31;
    const int q0 = blockIdx.x * 128, h = blockIdx.y, b = blockIdx.z;
    const size_t bh = (size_t)b * HH + h;
    const int R0 = wid * 16;

    const __half* Qf = g_qhf + (bh*TQ + q0)*64;
    const __half* Kf = g_khf + bh * (size_t)TKV * 64;
    const __half* Vf = g_vt  + bh * (size_t)64 * TKV;

    // Q (persistent, fp16)
#pragma unroll
    for (int i = 0; i < 4; i++){
        int f = i*256 + tid, r = f >> 3, kc = f & 7;
        cp16(sb + A_QH + SW128((uint32_t)(r*128 + kc*16)), Qf + f*8);
    }
    CP_COMMIT();

#define A_ISSUE(it) do { \
    int kv0_ = (it) * 128; \
    uint32_t base_ = sb + A_ST + ((it) % 3) * A_STAGE; \
    _Pragma("unroll") \
    for (int i_ = 0; i_ < 4; i_++){ \
        int f_ = i_*256 + tid; \
        int r_ = f_ >> 3, kc_ = f_ & 7; \
        cp16(base_ + SW128((uint32_t)(r_*128 + kc_*16)), Kf + (size_t)kv0_*64 + f_*8); \
        int r2_ = f_ >> 4, kc2_ = f_ & 15; \
        uint32_t d2_ = (uint32_t)(r2_*256 + ((kc2_ >> 3) << 7) + (((kc2_ & 7) ^ (r2_ & 7)) << 4)); \
        cp16(base_ + 16384 + d2_, Vf + (size_t)r2_*TKV + kv0_ + kc2_*8); \
    } \
    CP_COMMIT(); \
} while (0)

    A_ISSUE(0);
    A_ISSUE(1);

    float Oacc[8][4];
#pragma unroll
    for (int i = 0; i < 8; i++)
#pragma unroll
        for (int j = 0; j < 4; j++) Oacc[i][j] = 0.f;
    float rs0 = 0.f, rs1 = 0.f;

    const int r1l = R0 + (lane >> 2), r2l = r1l + 8;
    const int ar  = R0 + (lane & 15);
    const int akh = lane >> 4;
    const int bi  = lane & 7;
    const int grp = lane >> 3;
    const float* m1 = mask + (size_t)(q0 + r1l)*TKV + (lane & 3)*2;
    const float* m2 = m1 + 8*TKV;

    for (int it = 0; it < 16; it++){
        int kv0 = it * 128;
        if (it < 15) asm volatile("cp.async.wait_group 1;" ::: "memory");
        else         asm volatile("cp.async.wait_group 0;" ::: "memory");
        __syncthreads();
        uint32_t ba = sb + A_ST + (it % 3) * A_STAGE;

        // S = Q K^T (128x128), 1-pass fp16
        float Sacc[16][4];
#pragma unroll
        for (int i = 0; i < 16; i++)
#pragma unroll
            for (int j = 0; j < 4; j++) Sacc[i][j] = 0.f;
#pragma unroll
        for (int k16 = 0; k16 < 4; k16++){
            uint32_t aoff = SW128((uint32_t)(ar*128 + (k16*2 + akh)*16));
            uint32_t qh[4];
            ldm4(qh, sb + A_QH + aoff);
#pragma unroll
            for (int np = 0; np < 8; np++){
                int bn  = np*16 + (grp >> 1)*8 + bi;
                int bkc = k16*2 + (grp & 1);
                uint32_t boff = SW128((uint32_t)(bn*128 + bkc*16));
                uint32_t kh[4];
                ldm4(kh, ba + boff);
                mma_f16(Sacc[np*2],   qh, kh[0], kh[1]);
                mma_f16(Sacc[np*2+1], qh, kh[2], kh[3]);
            }
        }

        // P = exp(S + mask); row sums; store P fp16 to smem
#pragma unroll
        for (int nf = 0; nf < 16; nf++){
            float2 ma = *(const float2*)(m1 + kv0 + nf*8);
            float2 mb = *(const float2*)(m2 + kv0 + nf*8);
            float p0 = __expf(Sacc[nf][0] + ma.x);
            float p1 = __expf(Sacc[nf][1] + ma.y);
            float p2 = __expf(Sacc[nf][2] + mb.x);
            float p3 = __expf(Sacc[nf][3] + mb.y);
            rs0 += p0 + p1; rs1 += p2 + p3;
            __half2 h01 = __floats2half2_rn(p0, p1);
            __half2 h23 = __floats2half2_rn(p2, p3);
            uint32_t o1 = (uint32_t)(r1l*256 + ((nf >> 3) << 7) + (((nf & 7) ^ (r1l & 7)) << 4) + (lane & 3)*4);
            uint32_t o2 = (uint32_t)(r2l*256 + ((nf >> 3) << 7) + (((nf & 7) ^ (r2l & 7)) << 4) + (lane & 3)*4);
            sts32(sb + A_PH + o1, h2u(h01));
            sts32(sb + A_PH + o2, h2u(h23));
        }
        __syncwarp();   // P rows are warp-private

        // O += P V^T (128x64 over k=128), 1-pass fp16
#pragma unroll
        for (int k16 = 0; k16 < 8; k16++){
            int pkc = k16*2 + akh;
            uint32_t poff = (uint32_t)(ar*256 + ((pkc >> 3) << 7) + (((pkc & 7) ^ (ar & 7)) << 4));
            uint32_t ph[4];
            ldm4(ph, sb + A_PH + poff);
#pragma unroll
            for (int np = 0; np < 4; np++){
                int vn  = np*16 + (grp >> 1)*8 + bi;
                int vkc = k16*2 + (grp & 1);
                uint32_t voff = (uint32_t)(vn*256 + ((vkc >> 3) << 7) + (((vkc & 7) ^ (vn & 7)) << 4));
                uint32_t vh[4];
                ldm4(vh, ba + 16384 + voff);
                mma_f16(Oacc[np*2],   ph, vh[0], vh[1]);
                mma_f16(Oacc[np*2+1], ph, vh[2], vh[3]);
            }
        }

        // prefetch stage it+2 (buffer (it+2)%3 free: all warps passed this
        // iter's barrier, so iter it-1's reads of it are complete)
        if (it < 14) A_ISSUE(it + 2);
    }
#undef A_ISSUE

    // row-sum reduce across the 4 lanes sharing each row
    rs0 += __shfl_xor_sync(0xffffffffu, rs0, 1);
    rs0 += __shfl_xor_sync(0xffffffffu, rs0, 2);
    rs1 += __shfl_xor_sync(0xffffffffu, rs1, 1);
    rs1 += __shfl_xor_sync(0xffffffffu, rs1, 2);
    float inv0 = 1.f / rs0, inv1 = 1.f / rs1;

    // normalize + write attention output fp16 (head-major cols of [m,1024])
    size_t base1 = ((size_t)(b*TQ + q0 + r1l))*DD + h*64;
    size_t base2 = ((size_t)(b*TQ + q0 + r2l))*DD + h*64;
#pragma unroll
    for (int nf = 0; nf < 8; nf++){
        int c = nf*8 + (lane & 3)*2;
        *(__half2*)(g_av + base1 + c) = __floats2half2_rn(Oacc[nf][0]*inv0, Oacc[nf][1]*inv0);
        *(__half2*)(g_av + base2 + c) = __floats2half2_rn(Oacc[nf][2]*inv1, Oacc[nf][3]*inv1);
    }
}

// ---------------- launch ----------------------------------------------------
extern "C" void kernel_launch(void* const* d_in, const int* in_sizes, int n_in,
                              void* d_out, int out_size) {
    const float* x       = (const float*)d_in[0];
    const float* k_cache = (const float*)d_in[1];
    const float* v_cache = (const float*)d_in[2];
    const float* mask    = (const float*)d_in[3];
    const float* Wq      = (const float*)d_in[4];
    const float* bq      = (const float*)d_in[5];
    const float* Wk      = (const float*)d_in[6];
    const float* Wv      = (const float*)d_in[7];
    const float* bv      = (const float*)d_in[8];
    const float* Wo      = (const float*)d_in[9];
    const float* bo      = (const float*)d_in[10];

    float* outp = (float*)d_out;
    float* kout = outp + (size_t)BB * TQ * DD;
    float* vout = kout + (size_t)BB * TKV * DD;

    static int attr_done = 0;
    if (!attr_done){
        cudaFuncSetAttribute(gemm_tc, cudaFuncAttributeMaxDynamicSharedMemorySize, G_SMEM);
        cudaFuncSetAttribute(attn_tc, cudaFuncAttributeMaxDynamicSharedMemorySize, A_SMEM);
        attr_done = 1;
    }

    // 1) old cache rows -> output (+ K fp16 operands for old rows)
    {
        int n4 = BB * TQ * DD / 4;
        copy_old_cache<<<(n4 + 255)/256, 256>>>(
            (const float4*)k_cache, (const float4*)v_cache,
            (float4*)kout, (float4*)vout);
    }
    // 2) conversions: x -> fp16, all weights -> fp16 (one launch)
    conv_x<<<(BB*TQ*DD/4 + 255)/256, 256>>>((const float4*)x, BB*TQ*DD/4);
    conv_w4<<<dim3((DD*DD/4 + 255)/256, 4), 256>>>(
        (const float4*)Wq, (const float4*)Wk, (const float4*)Wv, (const float4*)Wo, DD*DD/4);
    // 3) QKV projections (K fp16 operands fused in mode-1 epilogue)
    gemm_tc<<<dim3(DD/128, BB*TQ/128, 3), 256, G_SMEM>>>(0, bq, bv, bo, kout, vout, outp);
    // 4) V cache -> transposed fp16 operand
    vconv<<<dim3(TKV/128, HH, BB), 256>>>(vout);
    // 5) attention
    attn_tc<<<dim3(TQ/128, HH, BB), 256, A_SMEM>>>(mask);
    // 6) output projection
    gemm_tc<<<dim3(DD/128, BB*TQ/128, 1), 256, G_SMEM>>>(3, bq, bv, bo, kout, vout, outp);
}

// round 11
// speedup vs baseline: 1.7419x; 1.7419x over previous
#include <cuda_runtime.h>
#include <cuda_fp16.h>
#include <cstdint>
#include <math.h>

#define BB 4
#define TQ 1024
#define TKV 2048
#define DD 1024
#define HH 16
#define DHD 64

// ---------------- device scratch (static; no allocations) -------------------
__device__ __half g_x[BB*TQ*DD];                     // x fp16
__device__ __half g_Wq[DD*DD], g_Wk[DD*DD], g_Wv[DD*DD], g_Wo[DD*DD];
__device__ __half g_qhf[BB*TQ*DD];                   // [b,h,tq,64], x0.125
__device__ __half g_khf[BB*TKV*DD];                  // [b,h,kv,64]
__device__ __half g_vt[BB*TKV*DD];                   // [b,h,64,kv] transposed
__device__ __half g_av[BB*TQ*DD];                    // attn out fp16 [m,1024]

// ---------------- helpers ---------------------------------------------------
__device__ __forceinline__ uint32_t smem_u32(const void* p){
    uint32_t a;
    asm("{ .reg .u64 t; cvta.to.shared.u64 t, %1; cvt.u32.u64 %0, t; }" : "=r"(a) : "l"(p));
    return a;
}
#define SW128(o) ((o) ^ (((o) >> 3) & 0x70))

__device__ __forceinline__ void ldm4(uint32_t* r, uint32_t addr){
    asm volatile("ldmatrix.sync.aligned.m8n8.x4.shared.b16 {%0,%1,%2,%3}, [%4];"
        : "=r"(r[0]), "=r"(r[1]), "=r"(r[2]), "=r"(r[3]) : "r"(addr));
}
__device__ __forceinline__ void mma_f16(float* c, const uint32_t* a, uint32_t b0, uint32_t b1){
    asm volatile("mma.sync.aligned.m16n8k16.row.col.f32.f16.f16.f32 "
        "{%0,%1,%2,%3}, {%4,%5,%6,%7}, {%8,%9}, {%0,%1,%2,%3};"
        : "+f"(c[0]), "+f"(c[1]), "+f"(c[2]), "+f"(c[3])
        : "r"(a[0]), "r"(a[1]), "r"(a[2]), "r"(a[3]), "r"(b0), "r"(b1));
}
__device__ __forceinline__ void cp16(uint32_t dst, const void* src){
    asm volatile("cp.async.cg.shared.global [%0], [%1], 16;" :: "r"(dst), "l"(src));
}
#define CP_COMMIT() asm volatile("cp.async.commit_group;")
__device__ __forceinline__ void sts32(uint32_t addr, uint32_t v){
    asm volatile("st.shared.b32 [%0], %1;" :: "r"(addr), "r"(v));
}
__device__ __forceinline__ uint32_t h2u(__half2 v){
    return *reinterpret_cast<uint32_t*>(&v);
}

// ---------------- small prep kernels ---------------------------------------
__global__ void copy_old_cache(const float4* __restrict__ ksrc,
                               const float4* __restrict__ vsrc,
                               float4* __restrict__ kdst,
                               float4* __restrict__ vdst){
    int i = blockIdx.x * blockDim.x + threadIdx.x;
    const int per_b = TQ * DD / 4;
    if (i >= BB * per_b) return;
    int b = i / per_b;
    int rem = i - b * per_b;
    size_t idx = (size_t)b * (TKV * DD / 4) + rem;
    float4 kv4 = ksrc[idx];
    kdst[idx] = kv4;
    vdst[idx] = vsrc[idx];
    int t = rem >> 8;
    int d = (rem & 255) * 4;
    int h = d >> 6, dh = d & 63;
    size_t o = (((size_t)b*HH + h)*TKV + t)*64 + dh;
    *(__half2*)(g_khf + o)     = __floats2half2_rn(kv4.x, kv4.y);
    *(__half2*)(g_khf + o + 2) = __floats2half2_rn(kv4.z, kv4.w);
}

__global__ void conv_x(const float4* __restrict__ src, int n4){
    int i = blockIdx.x * blockDim.x + threadIdx.x;
    if (i >= n4) return;
    float4 v = src[i];
    ((__half2*)g_x)[i*2+0] = __floats2half2_rn(v.x, v.y);
    ((__half2*)g_x)[i*2+1] = __floats2half2_rn(v.z, v.w);
}

__global__ void conv_w4(const float4* __restrict__ Wq, const float4* __restrict__ Wk,
                        const float4* __restrict__ Wv, const float4* __restrict__ Wo,
                        int n4){
    int i = blockIdx.x * blockDim.x + threadIdx.x;
    if (i >= n4) return;
    const float4* src;
    __half* W;
    switch (blockIdx.y){
        case 0: src = Wq; W = g_Wq; break;
        case 1: src = Wk; W = g_Wk; break;
        case 2: src = Wv; W = g_Wv; break;
        default:src = Wo; W = g_Wo; break;
    }
    float4 v = src[i];
    ((__half2*)W)[i*2+0] = __floats2half2_rn(v.x, v.y);
    ((__half2*)W)[i*2+1] = __floats2half2_rn(v.z, v.w);
}

__global__ void vconv(const float* __restrict__ vc){
    __shared__ float t[128][65];
    int kv0 = blockIdx.x * 128, h = blockIdx.y, b = blockIdx.z;
    int tid = threadIdx.x;
    for (int i = tid; i < 128*16; i += 256){
        int r = i >> 4, c4 = i & 15;
        float4 v = *(const float4*)(vc + ((size_t)(b*TKV + kv0 + r))*DD + h*64 + c4*4);
        t[r][c4*4+0] = v.x; t[r][c4*4+1] = v.y; t[r][c4*4+2] = v.z; t[r][c4*4+3] = v.w;
    }
    __syncthreads();
    for (int i = tid; i < 64*128; i += 256){
        int dh = i >> 7, j = i & 127;
        size_t o = (((size_t)b*HH + h)*64 + dh)*TKV + kv0 + j;
        g_vt[o] = __float2half_rn(t[j][dh]);
    }
}

// ---------------- fp16 1-pass projection GEMM (m32n64 warp tiles) -----------
// smem: 2 stages x {A 16K, W 16K} = 65536; target 2 blocks/SM
#define G_STAGE 32768
#define G_SMEM  65536

__global__ void __launch_bounds__(256, 2) gemm_tc(int mode_base,
    const float* __restrict__ bq, const float* __restrict__ bvv, const float* __restrict__ bo,
    float* __restrict__ kout, float* __restrict__ vout, float* __restrict__ outp){
    extern __shared__ char sm[];
    const int mode = mode_base + blockIdx.z;
    const __half *A, *W;
    const float* bias;
    if (mode == 0)      { A=g_x;  W=g_Wq; bias=bq;  }
    else if (mode == 1) { A=g_x;  W=g_Wk; bias=0;   }
    else if (mode == 2) { A=g_x;  W=g_Wv; bias=bvv; }
    else                { A=g_av; W=g_Wo; bias=bo;  }

    uint32_t sb = smem_u32(sm);
    const int tid = threadIdx.x, wid = tid >> 5, lane = tid & 31;
    const int m0 = blockIdx.y * 128, n0 = blockIdx.x * 128;
    const int mg = wid & 3, ngr = wid >> 2;
    const int R0 = mg * 32, C0 = ngr * 64;

    const __half* srcs[2] = { A + (size_t)m0*DD, W + (size_t)n0*DD };
    const int lr = tid >> 3, lkc = tid & 7;

#define G_ISSUE(ch, buf) do { \
    int k0_ = (ch) * 64; \
    _Pragma("unroll") \
    for (int t2 = 0; t2 < 2; t2++){ \
        uint32_t base_ = sb + (buf)*G_STAGE + t2*16384; \
        _Pragma("unroll") \
        for (int i_ = 0; i_ < 4; i_++){ \
            int r_ = lr + i_*32; \
            cp16(base_ + SW128((uint32_t)(r_*128 + lkc*16)), \
                 srcs[t2] + (size_t)r_*DD + k0_ + lkc*8); \
        } \
    } \
    CP_COMMIT(); \
} while (0)

    G_ISSUE(0, 0);
    G_ISSUE(1, 1);

    float acc[16][4];    // [i*8 + np*2 + h]: i = m-frag (rows R0+i*16..), np = n16, h = n8 half
#pragma unroll
    for (int i = 0; i < 16; i++)
#pragma unroll
        for (int j = 0; j < 4; j++) acc[i][j] = 0.f;

    const int ar  = lane & 15;
    const int akh = lane >> 4;
    const int bi  = lane & 7;
    const int grp = lane >> 3;

    for (int ch = 0; ch < 16; ch++){
        if (ch == 15) asm volatile("cp.async.wait_group 0;" ::: "memory");
        else          asm volatile("cp.async.wait_group 1;" ::: "memory");
        __syncthreads();
        uint32_t ba = sb + (ch & 1) * G_STAGE;
#pragma unroll
        for (int k16 = 0; k16 < 4; k16++){
            uint32_t a0[4], a1[4];
            ldm4(a0, ba + SW128((uint32_t)((R0 + ar)*128      + (k16*2 + akh)*16)));
            ldm4(a1, ba + SW128((uint32_t)((R0 + 16 + ar)*128 + (k16*2 + akh)*16)));
#pragma unroll
            for (int np = 0; np < 4; np++){
                int bn  = C0 + np*16 + (grp >> 1)*8 + bi;
                int bkc = k16*2 + (grp & 1);
                uint32_t w[4];
                ldm4(w, ba + 16384 + SW128((uint32_t)(bn*128 + bkc*16)));
                mma_f16(acc[np*2],       a0, w[0], w[1]);
                mma_f16(acc[np*2+1],     a0, w[2], w[3]);
                mma_f16(acc[8 + np*2],   a1, w[0], w[1]);
                mma_f16(acc[8 + np*2+1], a1, w[2], w[3]);
            }
        }
        __syncthreads();
        if (ch + 2 < 16) G_ISSUE(ch + 2, ch & 1);
    }
#undef G_ISSUE

    // epilogue: warp covers rows m0+R0..+31, cols n0+C0..+63
#pragma unroll
    for (int i = 0; i < 2; i++){
        const int r1 = m0 + R0 + i*16 + (lane >> 2), r2 = r1 + 8;
#pragma unroll
        for (int nf = 0; nf < 8; nf++){
            int idx = i*8 + nf;
            int c = n0 + C0 + nf*8 + (lane & 3)*2;
            float v0 = acc[idx][0], v1 = acc[idx][1], v2 = acc[idx][2], v3 = acc[idx][3];
            if (bias){
                float2 bb = *(const float2*)(bias + c);
                v0 += bb.x; v1 += bb.y; v2 += bb.x; v3 += bb.y;
            }
            if (mode == 0){
                v0 *= 0.125f; v1 *= 0.125f; v2 *= 0.125f; v3 *= 0.125f;
                int h = c >> 6, dh = c & 63;
#pragma unroll
                for (int rr = 0; rr < 2; rr++){
                    int row = rr ? r2 : r1;
                    float a = rr ? v2 : v0, b2 = rr ? v3 : v1;
                    int b = row >> 10, q = row & 1023;
                    size_t o = (((size_t)b*HH + h)*TQ + q)*64 + dh;
                    *(__half2*)(g_qhf + o) = __floats2half2_rn(a, b2);
                }
            } else if (mode == 3){
                *(float2*)(outp + (size_t)r1*DD + c) = make_float2(v0, v1);
                *(float2*)(outp + (size_t)r2*DD + c) = make_float2(v2, v3);
            } else {
                float* dst = (mode == 1) ? kout : vout;
                int h = c >> 6, dh = c & 63;
#pragma unroll
                for (int rr = 0; rr < 2; rr++){
                    int row = rr ? r2 : r1;
                    float a = rr ? v2 : v0, b2 = rr ? v3 : v1;
                    int b = row >> 10, q = row & 1023;
                    size_t o = ((size_t)b*TKV + TQ + q)*DD + c;
                    *(float2*)(dst + o) = make_float2(a, b2);
                    if (mode == 1){
                        size_t ko = (((size_t)b*HH + h)*TKV + TQ + q)*64 + dh;
                        *(__half2*)(g_khf + ko) = __floats2half2_rn(a, b2);
                    }
                }
            }
        }
    }
}

// ---------------- attention (fp16, m32n64 warp tiles) ------------------------
// smem: Q 16K @0 | P/Obuf 34K @16384 | ls 1K @51200 | 3 stages x 32K @52224
#define A_Q  0
#define A_P  16384
#define A_LS 51200
#define A_ST 52224
#define A_STAGE 32768
#define A_SMEM (52224 + 3*32768)     // 150528 (147KB)
#define OBS 272                       // Obuf row stride bytes (conflict-free)

__global__ void __launch_bounds__(256, 1) attn_tc(const float* __restrict__ mask){
    extern __shared__ char sm[];
    uint32_t sb = smem_u32(sm);
    const int tid = threadIdx.x, wid = tid >> 5, lane = tid & 31;
    const int q0 = blockIdx.x * 128, h = blockIdx.y, b = blockIdx.z;
    const size_t bh = (size_t)b * HH + h;
    const int mg = wid & 3, ngr = wid >> 2;
    const int R0 = mg * 32, C0 = ngr * 64;

    const __half* Qf = g_qhf + (bh*TQ + q0)*64;
    const __half* Kf = g_khf + bh * (size_t)TKV * 64;
    const __half* Vf = g_vt  + bh * (size_t)64 * TKV;

    // Q (persistent)
#pragma unroll
    for (int i = 0; i < 4; i++){
        int f = i*256 + tid, r = f >> 3, kc = f & 7;
        cp16(sb + A_Q + SW128((uint32_t)(r*128 + kc*16)), Qf + f*8);
    }
    CP_COMMIT();

#define A_ISSUE(it) do { \
    int kv0_ = (it) * 128; \
    uint32_t base_ = sb + A_ST + ((it) % 3) * A_STAGE; \
    _Pragma("unroll") \
    for (int i_ = 0; i_ < 4; i_++){ \
        int f_ = i_*256 + tid; \
        int r_ = f_ >> 3, kc_ = f_ & 7; \
        cp16(base_ + SW128((uint32_t)(r_*128 + kc_*16)), Kf + (size_t)kv0_*64 + f_*8); \
        int r2_ = f_ >> 4, kc2_ = f_ & 15; \
        uint32_t d2_ = (uint32_t)(r2_*256 + ((kc2_ >> 3) << 7) + (((kc2_ & 7) ^ (r2_ & 7)) << 4)); \
        cp16(base_ + 16384 + d2_, Vf + (size_t)r2_*TKV + kv0_ + kc2_*8); \
    } \
    CP_COMMIT(); \
} while (0)

    A_ISSUE(0);
    A_ISSUE(1);

    float Oacc[16][4];
#pragma unroll
    for (int i = 0; i < 16; i++)
#pragma unroll
        for (int j = 0; j < 4; j++) Oacc[i][j] = 0.f;
    float rs[4] = {0.f, 0.f, 0.f, 0.f};   // rows R0+(lane>>2)+{0,8,16,24} x warp's col half

    const int ar  = lane & 15;
    const int akh = lane >> 4;
    const int bi  = lane & 7;
    const int grp = lane >> 3;

    const float* mrow[4];
#pragma unroll
    for (int j = 0; j < 4; j++)
        mrow[j] = mask + (size_t)(q0 + R0 + (lane >> 2) + j*8)*TKV + C0 + (lane & 3)*2;

    for (int it = 0; it < 16; it++){
        int kv0 = it * 128;
        if (it < 15) asm volatile("cp.async.wait_group 1;" ::: "memory");
        else         asm volatile("cp.async.wait_group 0;" ::: "memory");
        __syncthreads();
        uint32_t ba = sb + A_ST + (it % 3) * A_STAGE;

        // S = Q K^T: warp computes rows R0..R0+31, kv cols C0..C0+63
        float Sacc[16][4];
#pragma unroll
        for (int i = 0; i < 16; i++)
#pragma unroll
            for (int j = 0; j < 4; j++) Sacc[i][j] = 0.f;
#pragma unroll
        for (int k16 = 0; k16 < 4; k16++){
            uint32_t q0f[4], q1f[4];
            ldm4(q0f, sb + A_Q + SW128((uint32_t)((R0 + ar)*128      + (k16*2 + akh)*16)));
            ldm4(q1f, sb + A_Q + SW128((uint32_t)((R0 + 16 + ar)*128 + (k16*2 + akh)*16)));
#pragma unroll
            for (int np = 0; np < 4; np++){
                int bn  = C0 + np*16 + (grp >> 1)*8 + bi;
                int bkc = k16*2 + (grp & 1);
                uint32_t kf[4];
                ldm4(kf, ba + SW128((uint32_t)(bn*128 + bkc*16)));
                mma_f16(Sacc[np*2],       q0f, kf[0], kf[1]);
                mma_f16(Sacc[np*2+1],     q0f, kf[2], kf[3]);
                mma_f16(Sacc[8 + np*2],   q1f, kf[0], kf[1]);
                mma_f16(Sacc[8 + np*2+1], q1f, kf[2], kf[3]);
            }
        }

        // P = exp(S + mask); partial row sums; store P fp16 to shared
#pragma unroll
        for (int i = 0; i < 2; i++){
            int row1 = R0 + i*16 + (lane >> 2), row2 = row1 + 8;
#pragma unroll
            for (int nf = 0; nf < 8; nf++){
                int idx = i*8 + nf;
                float2 ma = *(const float2*)(mrow[i*2]     + kv0 + nf*8);
                float2 mb = *(const float2*)(mrow[i*2 + 1] + kv0 + nf*8);
                float p0 = __expf(Sacc[idx][0] + ma.x);
                float p1 = __expf(Sacc[idx][1] + ma.y);
                float p2 = __expf(Sacc[idx][2] + mb.x);
                float p3 = __expf(Sacc[idx][3] + mb.y);
                rs[i*2]     += p0 + p1;
                rs[i*2 + 1] += p2 + p3;
                __half2 h01 = __floats2half2_rn(p0, p1);
                __half2 h23 = __floats2half2_rn(p2, p3);
                int c8 = ngr*8 + nf;     // global 8-col group 0..15
                uint32_t o1 = (uint32_t)(row1*256 + ((c8 >> 3) << 7) + (((c8 & 7) ^ (row1 & 7)) << 4) + (lane & 3)*4);
                uint32_t o2 = (uint32_t)(row2*256 + ((c8 >> 3) << 7) + (((c8 & 7) ^ (row2 & 7)) << 4) + (lane & 3)*4);
                sts32(sb + A_P + o1, h2u(h01));
                sts32(sb + A_P + o2, h2u(h23));
            }
        }
        __syncthreads();   // P now cross-warp shared

        // O += P V^T: warp computes rows R0..R0+31, dh cols 0..63, k-half ngr
#pragma unroll
        for (int kk = 0; kk < 4; kk++){
            int k16 = ngr*4 + kk;
            int pkc = k16*2 + akh;
            int pr1 = R0 + ar, pr2 = R0 + 16 + ar;
            uint32_t p0f[4], p1f[4];
            ldm4(p0f, sb + A_P + (uint32_t)(pr1*256 + ((pkc >> 3) << 7) + (((pkc & 7) ^ (pr1 & 7)) << 4)));
            ldm4(p1f, sb + A_P + (uint32_t)(pr2*256 + ((pkc >> 3) << 7) + (((pkc & 7) ^ (pr2 & 7)) << 4)));
#pragma unroll
            for (int np = 0; np < 4; np++){
                int vn  = np*16 + (grp >> 1)*8 + bi;
                int vkc = k16*2 + (grp & 1);
                uint32_t vf[4];
                ldm4(vf, ba + 16384 + (uint32_t)(vn*256 + ((vkc >> 3) << 7) + (((vkc & 7) ^ (vn & 7)) << 4)));
                mma_f16(Oacc[np*2],       p0f, vf[0], vf[1]);
                mma_f16(Oacc[np*2+1],     p0f, vf[2], vf[3]);
                mma_f16(Oacc[8 + np*2],   p1f, vf[0], vf[1]);
                mma_f16(Oacc[8 + np*2+1], p1f, vf[2], vf[3]);
            }
        }

        if (it < 14) A_ISSUE(it + 2);
    }
#undef A_ISSUE

    // combine partial row sums (4 lanes per row, then across col-half warps)
#pragma unroll
    for (int j = 0; j < 4; j++){
        rs[j] += __shfl_xor_sync(0xffffffffu, rs[j], 1);
        rs[j] += __shfl_xor_sync(0xffffffffu, rs[j], 2);
    }
    if ((lane & 3) == 0){
        int r = R0 + (lane >> 2);
        float* lsp = (float*)(sm + A_LS);
#pragma unroll
        for (int j = 0; j < 4; j++)
            lsp[(r + j*8)*2 + ngr] = rs[j];
    }
    __syncthreads();   // all PV reads of P done; ls visible

    // reduce O across the two k-half warps via Obuf (overlaying P region)
    if (ngr == 1){
#pragma unroll
        for (int i = 0; i < 2; i++){
            int r1 = R0 + i*16 + (lane >> 2), r2 = r1 + 8;
#pragma unroll
            for (int nf = 0; nf < 8; nf++){
                int idx = i*8 + nf;
                int c = nf*8 + (lane & 3)*2;
                *(float2*)(sm + A_P + r1*OBS + c*4) = make_float2(Oacc[idx][0], Oacc[idx][1]);
                *(float2*)(sm + A_P + r2*OBS + c*4) = make_float2(Oacc[idx][2], Oacc[idx][3]);
            }
        }
    }
    __syncthreads();
    if (ngr == 0){
        const float* lsp = (const float*)(sm + A_LS);
#pragma unroll
        for (int i = 0; i < 2; i++){
            int r1 = R0 + i*16 + (lane >> 2), r2 = r1 + 8;
            float inv1 = 1.f / (lsp[r1*2] + lsp[r1*2+1]);
            float inv2 = 1.f / (lsp[r2*2] + lsp[r2*2+1]);
            size_t base1 = ((size_t)(b*TQ + q0 + r1))*DD + h*64;
            size_t base2 = ((size_t)(b*TQ + q0 + r2))*DD + h*64;
#pragma unroll
            for (int nf = 0; nf < 8; nf++){
                int idx = i*8 + nf;
                int c = nf*8 + (lane & 3)*2;
                float2 o1 = *(float2*)(sm + A_P + r1*OBS + c*4);
                float2 o2 = *(float2*)(sm + A_P + r2*OBS + c*4);
                *(__half2*)(g_av + base1 + c) =
                    __floats2half2_rn((Oacc[idx][0] + o1.x)*inv1, (Oacc[idx][1] + o1.y)*inv1);
                *(__half2*)(g_av + base2 + c) =
                    __floats2half2_rn((Oacc[idx][2] + o2.x)*inv2, (Oacc[idx][3] + o2.y)*inv2);
            }
        }
    }
}

// ---------------- launch ----------------------------------------------------
extern "C" void kernel_launch(void* const* d_in, const int* in_sizes, int n_in,
                              void* d_out, int out_size) {
    const float* x       = (const float*)d_in[0];
    const float* k_cache = (const float*)d_in[1];
    const float* v_cache = (const float*)d_in[2];
    const float* mask    = (const float*)d_in[3];
    const float* Wq      = (const float*)d_in[4];
    const float* bq      = (const float*)d_in[5];
    const float* Wk      = (const float*)d_in[6];
    const float* Wv      = (const float*)d_in[7];
    const float* bv      = (const float*)d_in[8];
    const float* Wo      = (const float*)d_in[9];
    const float* bo      = (const float*)d_in[10];

    float* outp = (float*)d_out;
    float* kout = outp + (size_t)BB * TQ * DD;
    float* vout = kout + (size_t)BB * TKV * DD;

    static int attr_done = 0;
    if (!attr_done){
        cudaFuncSetAttribute(gemm_tc, cudaFuncAttributeMaxDynamicSharedMemorySize, G_SMEM);
        cudaFuncSetAttribute(attn_tc, cudaFuncAttributeMaxDynamicSharedMemorySize, A_SMEM);
        attr_done = 1;
    }

    // 1) old cache rows -> output (+ K fp16 operands for old rows)
    {
        int n4 = BB * TQ * DD / 4;
        copy_old_cache<<<(n4 + 255)/256, 256>>>(
            (const float4*)k_cache, (const float4*)v_cache,
            (float4*)kout, (float4*)vout);
    }
    // 2) conversions
    conv_x<<<(BB*TQ*DD/4 + 255)/256, 256>>>((const float4*)x, BB*TQ*DD/4);
    conv_w4<<<dim3((DD*DD/4 + 255)/256, 4), 256>>>(
        (const float4*)Wq, (const float4*)Wk, (const float4*)Wv, (const float4*)Wo, DD*DD/4);
    // 3) QKV projections
    gemm_tc<<<dim3(DD/128, BB*TQ/128, 3), 256, G_SMEM>>>(0, bq, bv, bo, kout, vout, outp);
    // 4) V cache -> transposed fp16 operand
    vconv<<<dim3(TKV/128, HH, BB), 256>>>(vout);
    // 5) attention
    attn_tc<<<dim3(TQ/128, HH, BB), 256, A_SMEM>>>(mask);
    // 6) output projection
    gemm_tc<<<dim3(DD/128, BB*TQ/128, 1), 256, G_SMEM>>>(3, bq, bv, bo, kout, vout, outp);
}

// round 12
// speedup vs baseline: 1.8173x; 1.0433x over previous
#include <cuda_runtime.h>
#include <cuda_fp16.h>
#include <cstdint>
#include <math.h>

#define BB 4
#define TQ 1024
#define TKV 2048
#define DD 1024
#define HH 16
#define DHD 64

// ---------------- device scratch (static; no allocations) -------------------
__device__ __half g_x[BB*TQ*DD];                     // x fp16
__device__ __half g_Wq[DD*DD], g_Wk[DD*DD], g_Wv[DD*DD], g_Wo[DD*DD];
__device__ __half g_qhf[BB*TQ*DD];                   // [b,h,tq,64], x0.125
__device__ __half g_khf[BB*TKV*DD];                  // [b,h,kv,64]
__device__ __half g_vt[BB*TKV*DD];                   // [b,h,64,kv] transposed
__device__ __half g_av[BB*TQ*DD];                    // attn out fp16 [m,1024]

// ---------------- helpers ---------------------------------------------------
__device__ __forceinline__ uint32_t smem_u32(const void* p){
    uint32_t a;
    asm("{ .reg .u64 t; cvta.to.shared.u64 t, %1; cvt.u32.u64 %0, t; }" : "=r"(a) : "l"(p));
    return a;
}
#define SW128(o) ((o) ^ (((o) >> 3) & 0x70))

__device__ __forceinline__ void ldm4(uint32_t* r, uint32_t addr){
    asm volatile("ldmatrix.sync.aligned.m8n8.x4.shared.b16 {%0,%1,%2,%3}, [%4];"
        : "=r"(r[0]), "=r"(r[1]), "=r"(r[2]), "=r"(r[3]) : "r"(addr));
}
__device__ __forceinline__ void mma_f16(float* c, const uint32_t* a, uint32_t b0, uint32_t b1){
    asm volatile("mma.sync.aligned.m16n8k16.row.col.f32.f16.f16.f32 "
        "{%0,%1,%2,%3}, {%4,%5,%6,%7}, {%8,%9}, {%0,%1,%2,%3};"
        : "+f"(c[0]), "+f"(c[1]), "+f"(c[2]), "+f"(c[3])
        : "r"(a[0]), "r"(a[1]), "r"(a[2]), "r"(a[3]), "r"(b0), "r"(b1));
}
__device__ __forceinline__ void cp16(uint32_t dst, const void* src){
    asm volatile("cp.async.cg.shared.global [%0], [%1], 16;" :: "r"(dst), "l"(src));
}
#define CP_COMMIT() asm volatile("cp.async.commit_group;")
__device__ __forceinline__ uint32_t h2u(__half2 v){
    return *reinterpret_cast<uint32_t*>(&v);
}

// ---------------- small prep kernels ---------------------------------------
__global__ void copy_old_cache(const float4* __restrict__ ksrc,
                               const float4* __restrict__ vsrc,
                               float4* __restrict__ kdst,
                               float4* __restrict__ vdst){
    int i = blockIdx.x * blockDim.x + threadIdx.x;
    const int per_b = TQ * DD / 4;
    if (i >= BB * per_b) return;
    int b = i / per_b;
    int rem = i - b * per_b;
    size_t idx = (size_t)b * (TKV * DD / 4) + rem;
    float4 kv4 = ksrc[idx];
    kdst[idx] = kv4;
    vdst[idx] = vsrc[idx];
    int t = rem >> 8;
    int d = (rem & 255) * 4;
    int h = d >> 6, dh = d & 63;
    size_t o = (((size_t)b*HH + h)*TKV + t)*64 + dh;
    *(__half2*)(g_khf + o)     = __floats2half2_rn(kv4.x, kv4.y);
    *(__half2*)(g_khf + o + 2) = __floats2half2_rn(kv4.z, kv4.w);
}

__global__ void conv_x(const float4* __restrict__ src, int n4){
    int i = blockIdx.x * blockDim.x + threadIdx.x;
    if (i >= n4) return;
    float4 v = src[i];
    ((__half2*)g_x)[i*2+0] = __floats2half2_rn(v.x, v.y);
    ((__half2*)g_x)[i*2+1] = __floats2half2_rn(v.z, v.w);
}

__global__ void conv_w4(const float4* __restrict__ Wq, const float4* __restrict__ Wk,
                        const float4* __restrict__ Wv, const float4* __restrict__ Wo,
                        int n4){
    int i = blockIdx.x * blockDim.x + threadIdx.x;
    if (i >= n4) return;
    const float4* src;
    __half* W;
    switch (blockIdx.y){
        case 0: src = Wq; W = g_Wq; break;
        case 1: src = Wk; W = g_Wk; break;
        case 2: src = Wv; W = g_Wv; break;
        default:src = Wo; W = g_Wo; break;
    }
    float4 v = src[i];
    ((__half2*)W)[i*2+0] = __floats2half2_rn(v.x, v.y);
    ((__half2*)W)[i*2+1] = __floats2half2_rn(v.z, v.w);
}

__global__ void vconv(const float* __restrict__ vc){
    __shared__ float t[128][65];
    int kv0 = blockIdx.x * 128, h = blockIdx.y, b = blockIdx.z;
    int tid = threadIdx.x;
    for (int i = tid; i < 128*16; i += 256){
        int r = i >> 4, c4 = i & 15;
        float4 v = *(const float4*)(vc + ((size_t)(b*TKV + kv0 + r))*DD + h*64 + c4*4);
        t[r][c4*4+0] = v.x; t[r][c4*4+1] = v.y; t[r][c4*4+2] = v.z; t[r][c4*4+3] = v.w;
    }
    __syncthreads();
    for (int i = tid; i < 64*128; i += 256){
        int dh = i >> 7, j = i & 127;
        size_t o = (((size_t)b*HH + h)*64 + dh)*TKV + kv0 + j;
        g_vt[o] = __float2half_rn(t[j][dh]);
    }
}

// ---------------- fp16 1-pass projection GEMM (m32n64 warp tiles) -----------
#define G_STAGE 32768
#define G_SMEM  65536

__global__ void __launch_bounds__(256, 2) gemm_tc(int mode_base,
    const float* __restrict__ bq, const float* __restrict__ bvv, const float* __restrict__ bo,
    float* __restrict__ kout, float* __restrict__ vout, float* __restrict__ outp){
    extern __shared__ char sm[];
    const int mode = mode_base + blockIdx.z;
    const __half *A, *W;
    const float* bias;
    if (mode == 0)      { A=g_x;  W=g_Wq; bias=bq;  }
    else if (mode == 1) { A=g_x;  W=g_Wk; bias=0;   }
    else if (mode == 2) { A=g_x;  W=g_Wv; bias=bvv; }
    else                { A=g_av; W=g_Wo; bias=bo;  }

    uint32_t sb = smem_u32(sm);
    const int tid = threadIdx.x, wid = tid >> 5, lane = tid & 31;
    const int m0 = blockIdx.y * 128, n0 = blockIdx.x * 128;
    const int mg = wid & 3, ngr = wid >> 2;
    const int R0 = mg * 32, C0 = ngr * 64;

    const __half* srcs[2] = { A + (size_t)m0*DD, W + (size_t)n0*DD };
    const int lr = tid >> 3, lkc = tid & 7;

#define G_ISSUE(ch, buf) do { \
    int k0_ = (ch) * 64; \
    _Pragma("unroll") \
    for (int t2 = 0; t2 < 2; t2++){ \
        uint32_t base_ = sb + (buf)*G_STAGE + t2*16384; \
        _Pragma("unroll") \
        for (int i_ = 0; i_ < 4; i_++){ \
            int r_ = lr + i_*32; \
            cp16(base_ + SW128((uint32_t)(r_*128 + lkc*16)), \
                 srcs[t2] + (size_t)r_*DD + k0_ + lkc*8); \
        } \
    } \
    CP_COMMIT(); \
} while (0)

    G_ISSUE(0, 0);
    G_ISSUE(1, 1);

    float acc[16][4];
#pragma unroll
    for (int i = 0; i < 16; i++)
#pragma unroll
        for (int j = 0; j < 4; j++) acc[i][j] = 0.f;

    const int ar  = lane & 15;
    const int akh = lane >> 4;
    const int bi  = lane & 7;
    const int grp = lane >> 3;

    for (int ch = 0; ch < 16; ch++){
        if (ch == 15) asm volatile("cp.async.wait_group 0;" ::: "memory");
        else          asm volatile("cp.async.wait_group 1;" ::: "memory");
        __syncthreads();
        uint32_t ba = sb + (ch & 1) * G_STAGE;
#pragma unroll
        for (int k16 = 0; k16 < 4; k16++){
            uint32_t a0[4], a1[4];
            ldm4(a0, ba + SW128((uint32_t)((R0 + ar)*128      + (k16*2 + akh)*16)));
            ldm4(a1, ba + SW128((uint32_t)((R0 + 16 + ar)*128 + (k16*2 + akh)*16)));
#pragma unroll
            for (int np = 0; np < 4; np++){
                int bn  = C0 + np*16 + (grp >> 1)*8 + bi;
                int bkc = k16*2 + (grp & 1);
                uint32_t w[4];
                ldm4(w, ba + 16384 + SW128((uint32_t)(bn*128 + bkc*16)));
                mma_f16(acc[np*2],       a0, w[0], w[1]);
                mma_f16(acc[np*2+1],     a0, w[2], w[3]);
                mma_f16(acc[8 + np*2],   a1, w[0], w[1]);
                mma_f16(acc[8 + np*2+1], a1, w[2], w[3]);
            }
        }
        __syncthreads();
        if (ch + 2 < 16) G_ISSUE(ch + 2, ch & 1);
    }
#undef G_ISSUE

    // epilogue: warp covers rows m0+R0..+31, cols n0+C0..+63
#pragma unroll
    for (int i = 0; i < 2; i++){
        const int r1 = m0 + R0 + i*16 + (lane >> 2), r2 = r1 + 8;
#pragma unroll
        for (int nf = 0; nf < 8; nf++){
            int idx = i*8 + nf;
            int c = n0 + C0 + nf*8 + (lane & 3)*2;
            float v0 = acc[idx][0], v1 = acc[idx][1], v2 = acc[idx][2], v3 = acc[idx][3];
            if (bias){
                float2 bb = *(const float2*)(bias + c);
                v0 += bb.x; v1 += bb.y; v2 += bb.x; v3 += bb.y;
            }
            if (mode == 0){
                v0 *= 0.125f; v1 *= 0.125f; v2 *= 0.125f; v3 *= 0.125f;
                int h = c >> 6, dh = c & 63;
#pragma unroll
                for (int rr = 0; rr < 2; rr++){
                    int row = rr ? r2 : r1;
                    float a = rr ? v2 : v0, b2 = rr ? v3 : v1;
                    int b = row >> 10, q = row & 1023;
                    size_t o = (((size_t)b*HH + h)*TQ + q)*64 + dh;
                    *(__half2*)(g_qhf + o) = __floats2half2_rn(a, b2);
                }
            } else if (mode == 3){
                *(float2*)(outp + (size_t)r1*DD + c) = make_float2(v0, v1);
                *(float2*)(outp + (size_t)r2*DD + c) = make_float2(v2, v3);
            } else {
                float* dst = (mode == 1) ? kout : vout;
                int h = c >> 6, dh = c & 63;
#pragma unroll
                for (int rr = 0; rr < 2; rr++){
                    int row = rr ? r2 : r1;
                    float a = rr ? v2 : v0, b2 = rr ? v3 : v1;
                    int b = row >> 10, q = row & 1023;
                    size_t o = ((size_t)b*TKV + TQ + q)*DD + c;
                    *(float2*)(dst + o) = make_float2(a, b2);
                    if (mode == 1){
                        size_t ko = (((size_t)b*HH + h)*TKV + TQ + q)*64 + dh;
                        *(__half2*)(g_khf + ko) = __floats2half2_rn(a, b2);
                    }
                }
            }
        }
    }
}

// ---------------- attention (fp16, register-resident P) ---------------------
// 8 warps x m16 q-rows; S = m16 x n128 per warp (P warp-private in regs);
// PV consumes S accum fragments directly as A-operands. One barrier per iter.
// smem: Q 16K @0 | 3 stages x 32K {K 16K, V 16K} @16384
#define A_Q  0
#define A_ST 16384
#define A_STAGE 32768
#define A_SMEM (16384 + 3*32768)     // 114688 (112KB)

__global__ void __launch_bounds__(256, 1) attn_tc(const float* __restrict__ mask){
    extern __shared__ char sm[];
    uint32_t sb = smem_u32(sm);
    const int tid = threadIdx.x, wid = tid >> 5, lane = tid & 31;
    const int q0 = blockIdx.x * 128, h = blockIdx.y, b = blockIdx.z;
    const size_t bh = (size_t)b * HH + h;
    const int R0 = wid * 16;

    const __half* Qf = g_qhf + (bh*TQ + q0)*64;
    const __half* Kf = g_khf + bh * (size_t)TKV * 64;
    const __half* Vf = g_vt  + bh * (size_t)64 * TKV;

    // Q (persistent)
#pragma unroll
    for (int i = 0; i < 4; i++){
        int f = i*256 + tid, r = f >> 3, kc = f & 7;
        cp16(sb + A_Q + SW128((uint32_t)(r*128 + kc*16)), Qf + f*8);
    }
    CP_COMMIT();

#define A_ISSUE(it) do { \
    int kv0_ = (it) * 128; \
    uint32_t base_ = sb + A_ST + ((it) % 3) * A_STAGE; \
    _Pragma("unroll") \
    for (int i_ = 0; i_ < 4; i_++){ \
        int f_ = i_*256 + tid; \
        int r_ = f_ >> 3, kc_ = f_ & 7; \
        cp16(base_ + SW128((uint32_t)(r_*128 + kc_*16)), Kf + (size_t)kv0_*64 + f_*8); \
        int r2_ = f_ >> 4, kc2_ = f_ & 15; \
        uint32_t d2_ = (uint32_t)(r2_*256 + ((kc2_ >> 3) << 7) + (((kc2_ & 7) ^ (r2_ & 7)) << 4)); \
        cp16(base_ + 16384 + d2_, Vf + (size_t)r2_*TKV + kv0_ + kc2_*8); \
    } \
    CP_COMMIT(); \
} while (0)

    A_ISSUE(0);
    A_ISSUE(1);

    float Oacc[8][4];
#pragma unroll
    for (int i = 0; i < 8; i++)
#pragma unroll
        for (int j = 0; j < 4; j++) Oacc[i][j] = 0.f;
    float rs0 = 0.f, rs1 = 0.f;

    const int ar  = lane & 15;
    const int akh = lane >> 4;
    const int bi  = lane & 7;
    const int grp = lane >> 3;
    const float* m1 = mask + (size_t)(q0 + R0 + (lane >> 2))*TKV + (lane & 3)*2;
    const float* m2 = m1 + 8*TKV;

    uint32_t qf[4][4];   // Q fragments, loaded once at it==0

    for (int it = 0; it < 16; it++){
        int kv0 = it * 128;
        if (it < 15) asm volatile("cp.async.wait_group 1;" ::: "memory");
        else         asm volatile("cp.async.wait_group 0;" ::: "memory");
        __syncthreads();
        uint32_t ba = sb + A_ST + (it % 3) * A_STAGE;

        if (it == 0){
#pragma unroll
            for (int k16 = 0; k16 < 4; k16++)
                ldm4(qf[k16], sb + A_Q + SW128((uint32_t)((R0 + ar)*128 + (k16*2 + akh)*16)));
        }

        // S = Q K^T, warp tile m16 x n128 in two n64 halves; exp + pack to regs
        uint32_t pkA[16], pkB[16];   // per n8-group: rows r / r+8 packed half2
#pragma unroll
        for (int h2 = 0; h2 < 2; h2++){
            float Sacc[8][4];
#pragma unroll
            for (int i = 0; i < 8; i++)
#pragma unroll
                for (int j = 0; j < 4; j++) Sacc[i][j] = 0.f;
#pragma unroll
            for (int k16 = 0; k16 < 4; k16++){
#pragma unroll
                for (int np = 0; np < 4; np++){
                    int bn  = h2*64 + np*16 + (grp >> 1)*8 + bi;
                    int bkc = k16*2 + (grp & 1);
                    uint32_t kf[4];
                    ldm4(kf, ba + SW128((uint32_t)(bn*128 + bkc*16)));
                    mma_f16(Sacc[np*2],   qf[k16], kf[0], kf[1]);
                    mma_f16(Sacc[np*2+1], qf[k16], kf[2], kf[3]);
                }
            }
#pragma unroll
            for (int nf = 0; nf < 8; nf++){
                int g = h2*8 + nf;
                const float* ma = m1 + kv0 + h2*64 + nf*8;
                const float* mb = m2 + kv0 + h2*64 + nf*8;
                float2 mav = *(const float2*)ma;
                float2 mbv = *(const float2*)mb;
                float p0 = __expf(Sacc[nf][0] + mav.x);
                float p1 = __expf(Sacc[nf][1] + mav.y);
                float p2 = __expf(Sacc[nf][2] + mbv.x);
                float p3 = __expf(Sacc[nf][3] + mbv.y);
                rs0 += p0 + p1; rs1 += p2 + p3;
                pkA[g] = h2u(__floats2half2_rn(p0, p1));
                pkB[g] = h2u(__floats2half2_rn(p2, p3));
            }
        }

        // O += P V^T: P fragments straight from registers
#pragma unroll
        for (int j = 0; j < 8; j++){
            uint32_t af[4] = { pkA[2*j], pkB[2*j], pkA[2*j + 1], pkB[2*j + 1] };
#pragma unroll
            for (int np = 0; np < 4; np++){
                int vn  = np*16 + (grp >> 1)*8 + bi;
                int vkc = j*2 + (grp & 1);
                uint32_t vf[4];
                ldm4(vf, ba + 16384 + (uint32_t)(vn*256 + ((vkc >> 3) << 7) + (((vkc & 7) ^ (vn & 7)) << 4)));
                mma_f16(Oacc[np*2],   af, vf[0], vf[1]);
                mma_f16(Oacc[np*2+1], af, vf[2], vf[3]);
            }
        }

        // prefetch stage it+2 (buffer free: all warps passed this iter's barrier)
        if (it < 14) A_ISSUE(it + 2);
    }
#undef A_ISSUE

    // row-sum reduce across the 4 lanes sharing each row
    rs0 += __shfl_xor_sync(0xffffffffu, rs0, 1);
    rs0 += __shfl_xor_sync(0xffffffffu, rs0, 2);
    rs1 += __shfl_xor_sync(0xffffffffu, rs1, 1);
    rs1 += __shfl_xor_sync(0xffffffffu, rs1, 2);
    float inv0 = 1.f / rs0, inv1 = 1.f / rs1;

    // normalize + write attention output fp16 (head-major cols of [m,1024])
    int r1 = R0 + (lane >> 2), r2 = r1 + 8;
    size_t base1 = ((size_t)(b*TQ + q0 + r1))*DD + h*64;
    size_t base2 = ((size_t)(b*TQ + q0 + r2))*DD + h*64;
#pragma unroll
    for (int nf = 0; nf < 8; nf++){
        int c = nf*8 + (lane & 3)*2;
        *(__half2*)(g_av + base1 + c) = __floats2half2_rn(Oacc[nf][0]*inv0, Oacc[nf][1]*inv0);
        *(__half2*)(g_av + base2 + c) = __floats2half2_rn(Oacc[nf][2]*inv1, Oacc[nf][3]*inv1);
    }
}

// ---------------- launch ----------------------------------------------------
extern "C" void kernel_launch(void* const* d_in, const int* in_sizes, int n_in,
                              void* d_out, int out_size) {
    const float* x       = (const float*)d_in[0];
    const float* k_cache = (const float*)d_in[1];
    const float* v_cache = (const float*)d_in[2];
    const float* mask    = (const float*)d_in[3];
    const float* Wq      = (const float*)d_in[4];
    const float* bq      = (const float*)d_in[5];
    const float* Wk      = (const float*)d_in[6];
    const float* Wv      = (const float*)d_in[7];
    const float* bv      = (const float*)d_in[8];
    const float* Wo      = (const float*)d_in[9];
    const float* bo      = (const float*)d_in[10];

    float* outp = (float*)d_out;
    float* kout = outp + (size_t)BB * TQ * DD;
    float* vout = kout + (size_t)BB * TKV * DD;

    static int attr_done = 0;
    if (!attr_done){
        cudaFuncSetAttribute(gemm_tc, cudaFuncAttributeMaxDynamicSharedMemorySize, G_SMEM);
        cudaFuncSetAttribute(attn_tc, cudaFuncAttributeMaxDynamicSharedMemorySize, A_SMEM);
        attr_done = 1;
    }

    // 1) old cache rows -> output (+ K fp16 operands for old rows)
    {
        int n4 = BB * TQ * DD / 4;
        copy_old_cache<<<(n4 + 255)/256, 256>>>(
            (const float4*)k_cache, (const float4*)v_cache,
            (float4*)kout, (float4*)vout);
    }
    // 2) conversions
    conv_x<<<(BB*TQ*DD/4 + 255)/256, 256>>>((const float4*)x, BB*TQ*DD/4);
    conv_w4<<<dim3((DD*DD/4 + 255)/256, 4), 256>>>(
        (const float4*)Wq, (const float4*)Wk, (const float4*)Wv, (const float4*)Wo, DD*DD/4);
    // 3) QKV projections
    gemm_tc<<<dim3(DD/128, BB*TQ/128, 3), 256, G_SMEM>>>(0, bq, bv, bo, kout, vout, outp);
    // 4) V cache -> transposed fp16 operand
    vconv<<<dim3(TKV/128, HH, BB), 256>>>(vout);
    // 5) attention
    attn_tc<<<dim3(TQ/128, HH, BB), 256, A_SMEM>>>(mask);
    // 6) output projection
    gemm_tc<<<dim3(DD/128, BB*TQ/128, 1), 256, G_SMEM>>>(3, bq, bv, bo, kout, vout, outp);
}

// round 14
// speedup vs baseline: 1.9120x; 1.0521x over previous
#include <cuda_runtime.h>
#include <cuda_fp16.h>
#include <cstdint>
#include <math.h>

#define BB 4
#define TQ 1024
#define TKV 2048
#define DD 1024
#define HH 16
#define DHD 64

// ---------------- device scratch (static; no allocations) -------------------
__device__ __half g_x[BB*TQ*DD];                     // x fp16
__device__ __half g_Wq[DD*DD], g_Wk[DD*DD], g_Wv[DD*DD], g_Wo[DD*DD];
__device__ __half g_qhf[BB*TQ*DD];                   // [b,h,tq,64], x0.125
__device__ __half g_khf[BB*TKV*DD];                  // [b,h,kv,64]
__device__ __half g_vt[BB*TKV*DD];                   // [b,h,64,kv] transposed
__device__ __half g_av[BB*TQ*DD];                    // attn out fp16 [m,1024]

// ---------------- helpers ---------------------------------------------------
__device__ __forceinline__ uint32_t smem_u32(const void* p){
    uint32_t a;
    asm("{ .reg .u64 t; cvta.to.shared.u64 t, %1; cvt.u32.u64 %0, t; }" : "=r"(a) : "l"(p));
    return a;
}
#define SW128(o) ((o) ^ (((o) >> 3) & 0x70))

__device__ __forceinline__ void ldm4(uint32_t* r, uint32_t addr){
    asm volatile("ldmatrix.sync.aligned.m8n8.x4.shared.b16 {%0,%1,%2,%3}, [%4];"
        : "=r"(r[0]), "=r"(r[1]), "=r"(r[2]), "=r"(r[3]) : "r"(addr));
}
__device__ __forceinline__ void mma_f16(float* c, const uint32_t* a, uint32_t b0, uint32_t b1){
    asm volatile("mma.sync.aligned.m16n8k16.row.col.f32.f16.f16.f32 "
        "{%0,%1,%2,%3}, {%4,%5,%6,%7}, {%8,%9}, {%0,%1,%2,%3};"
        : "+f"(c[0]), "+f"(c[1]), "+f"(c[2]), "+f"(c[3])
        : "r"(a[0]), "r"(a[1]), "r"(a[2]), "r"(a[3]), "r"(b0), "r"(b1));
}
__device__ __forceinline__ void cp16(uint32_t dst, const void* src){
    asm volatile("cp.async.cg.shared.global [%0], [%1], 16;" :: "r"(dst), "l"(src));
}
#define CP_COMMIT() asm volatile("cp.async.commit_group;")
__device__ __forceinline__ uint32_t h2u(__half2 v){
    return *reinterpret_cast<uint32_t*>(&v);
}

// ---------------- small prep kernels ---------------------------------------
__global__ void copy_old_cache(const float4* __restrict__ ksrc,
                               const float4* __restrict__ vsrc,
                               float4* __restrict__ kdst,
                               float4* __restrict__ vdst){
    int i = blockIdx.x * blockDim.x + threadIdx.x;
    const int per_b = TQ * DD / 4;
    if (i >= BB * per_b) return;
    int b = i / per_b;
    int rem = i - b * per_b;
    size_t idx = (size_t)b * (TKV * DD / 4) + rem;
    float4 kv4 = ksrc[idx];
    kdst[idx] = kv4;
    vdst[idx] = vsrc[idx];
    int t = rem >> 8;
    int d = (rem & 255) * 4;
    int h = d >> 6, dh = d & 63;
    size_t o = (((size_t)b*HH + h)*TKV + t)*64 + dh;
    *(__half2*)(g_khf + o)     = __floats2half2_rn(kv4.x, kv4.y);
    *(__half2*)(g_khf + o + 2) = __floats2half2_rn(kv4.z, kv4.w);
}

__global__ void conv_x(const float4* __restrict__ src, int n4){
    int i = blockIdx.x * blockDim.x + threadIdx.x;
    if (i >= n4) return;
    float4 v = src[i];
    ((__half2*)g_x)[i*2+0] = __floats2half2_rn(v.x, v.y);
    ((__half2*)g_x)[i*2+1] = __floats2half2_rn(v.z, v.w);
}

__global__ void conv_w4(const float4* __restrict__ Wq, const float4* __restrict__ Wk,
                        const float4* __restrict__ Wv, const float4* __restrict__ Wo,
                        int n4){
    int i = blockIdx.x * blockDim.x + threadIdx.x;
    if (i >= n4) return;
    const float4* src;
    __half* W;
    switch (blockIdx.y){
        case 0: src = Wq; W = g_Wq; break;
        case 1: src = Wk; W = g_Wk; break;
        case 2: src = Wv; W = g_Wv; break;
        default:src = Wo; W = g_Wo; break;
    }
    float4 v = src[i];
    ((__half2*)W)[i*2+0] = __floats2half2_rn(v.x, v.y);
    ((__half2*)W)[i*2+1] = __floats2half2_rn(v.z, v.w);
}

__global__ void vconv(const float* __restrict__ vc){
    __shared__ float t[128][65];
    int kv0 = blockIdx.x * 128, h = blockIdx.y, b = blockIdx.z;
    int tid = threadIdx.x;
    for (int i = tid; i < 128*16; i += 256){
        int r = i >> 4, c4 = i & 15;
        float4 v = *(const float4*)(vc + ((size_t)(b*TKV + kv0 + r))*DD + h*64 + c4*4);
        t[r][c4*4+0] = v.x; t[r][c4*4+1] = v.y; t[r][c4*4+2] = v.z; t[r][c4*4+3] = v.w;
    }
    __syncthreads();
    for (int i = tid; i < 64*128; i += 256){
        int dh = i >> 7, j = i & 127;
        size_t o = (((size_t)b*HH + h)*64 + dh)*TKV + kv0 + j;
        g_vt[o] = __float2half_rn(t[j][dh]);
    }
}

// ---------------- fp16 1-pass projection GEMM (m32n64 warp tiles) -----------
#define G_STAGE 32768
#define G_SMEM  65536

__global__ void __launch_bounds__(256, 2) gemm_tc(int mode_base,
    const float* __restrict__ bq, const float* __restrict__ bvv, const float* __restrict__ bo,
    float* __restrict__ kout, float* __restrict__ vout, float* __restrict__ outp){
    extern __shared__ char sm[];
    const int mode = mode_base + blockIdx.z;
    const __half *A, *W;
    const float* bias;
    if (mode == 0)      { A=g_x;  W=g_Wq; bias=bq;  }
    else if (mode == 1) { A=g_x;  W=g_Wk; bias=0;   }
    else if (mode == 2) { A=g_x;  W=g_Wv; bias=bvv; }
    else                { A=g_av; W=g_Wo; bias=bo;  }

    uint32_t sb = smem_u32(sm);
    const int tid = threadIdx.x, wid = tid >> 5, lane = tid & 31;
    const int m0 = blockIdx.y * 128, n0 = blockIdx.x * 128;
    const int mg = wid & 3, ngr = wid >> 2;
    const int R0 = mg * 32, C0 = ngr * 64;

    const __half* srcs[2] = { A + (size_t)m0*DD, W + (size_t)n0*DD };
    const int lr = tid >> 3, lkc = tid & 7;

#define G_ISSUE(ch, buf) do { \
    int k0_ = (ch) * 64; \
    _Pragma("unroll") \
    for (int t2 = 0; t2 < 2; t2++){ \
        uint32_t base_ = sb + (buf)*G_STAGE + t2*16384; \
        _Pragma("unroll") \
        for (int i_ = 0; i_ < 4; i_++){ \
            int r_ = lr + i_*32; \
            cp16(base_ + SW128((uint32_t)(r_*128 + lkc*16)), \
                 srcs[t2] + (size_t)r_*DD + k0_ + lkc*8); \
        } \
    } \
    CP_COMMIT(); \
} while (0)

    G_ISSUE(0, 0);
    G_ISSUE(1, 1);

    float acc[16][4];
#pragma unroll
    for (int i = 0; i < 16; i++)
#pragma unroll
        for (int j = 0; j < 4; j++) acc[i][j] = 0.f;

    const int ar  = lane & 15;
    const int akh = lane >> 4;
    const int bi  = lane & 7;
    const int grp = lane >> 3;

    for (int ch = 0; ch < 16; ch++){
        if (ch == 15) asm volatile("cp.async.wait_group 0;" ::: "memory");
        else          asm volatile("cp.async.wait_group 1;" ::: "memory");
        __syncthreads();
        uint32_t ba = sb + (ch & 1) * G_STAGE;
#pragma unroll
        for (int k16 = 0; k16 < 4; k16++){
            uint32_t a0[4], a1[4];
            ldm4(a0, ba + SW128((uint32_t)((R0 + ar)*128      + (k16*2 + akh)*16)));
            ldm4(a1, ba + SW128((uint32_t)((R0 + 16 + ar)*128 + (k16*2 + akh)*16)));
#pragma unroll
            for (int np = 0; np < 4; np++){
                int bn  = C0 + np*16 + (grp >> 1)*8 + bi;
                int bkc = k16*2 + (grp & 1);
                uint32_t w[4];
                ldm4(w, ba + 16384 + SW128((uint32_t)(bn*128 + bkc*16)));
                mma_f16(acc[np*2],       a0, w[0], w[1]);
                mma_f16(acc[np*2+1],     a0, w[2], w[3]);
                mma_f16(acc[8 + np*2],   a1, w[0], w[1]);
                mma_f16(acc[8 + np*2+1], a1, w[2], w[3]);
            }
        }
        __syncthreads();
        if (ch + 2 < 16) G_ISSUE(ch + 2, ch & 1);
    }
#undef G_ISSUE

    // epilogue: warp covers rows m0+R0..+31, cols n0+C0..+63
#pragma unroll
    for (int i = 0; i < 2; i++){
        const int r1 = m0 + R0 + i*16 + (lane >> 2), r2 = r1 + 8;
#pragma unroll
        for (int nf = 0; nf < 8; nf++){
            int idx = i*8 + nf;
            int c = n0 + C0 + nf*8 + (lane & 3)*2;
            float v0 = acc[idx][0], v1 = acc[idx][1], v2 = acc[idx][2], v3 = acc[idx][3];
            if (bias){
                float2 bb = *(const float2*)(bias + c);
                v0 += bb.x; v1 += bb.y; v2 += bb.x; v3 += bb.y;
            }
            if (mode == 0){
                v0 *= 0.125f; v1 *= 0.125f; v2 *= 0.125f; v3 *= 0.125f;
                int h = c >> 6, dh = c & 63;
#pragma unroll
                for (int rr = 0; rr < 2; rr++){
                    int row = rr ? r2 : r1;
                    float a = rr ? v2 : v0, b2 = rr ? v3 : v1;
                    int b = row >> 10, q = row & 1023;
                    size_t o = (((size_t)b*HH + h)*TQ + q)*64 + dh;
                    *(__half2*)(g_qhf + o) = __floats2half2_rn(a, b2);
                }
            } else if (mode == 3){
                *(float2*)(outp + (size_t)r1*DD + c) = make_float2(v0, v1);
                *(float2*)(outp + (size_t)r2*DD + c) = make_float2(v2, v3);
            } else {
                float* dst = (mode == 1) ? kout : vout;
                int h = c >> 6, dh = c & 63;
#pragma unroll
                for (int rr = 0; rr < 2; rr++){
                    int row = rr ? r2 : r1;
                    float a = rr ? v2 : v0, b2 = rr ? v3 : v1;
                    int b = row >> 10, q = row & 1023;
                    size_t o = ((size_t)b*TKV + TQ + q)*DD + c;
                    *(float2*)(dst + o) = make_float2(a, b2);
                    if (mode == 1){
                        size_t ko = (((size_t)b*HH + h)*TKV + TQ + q)*64 + dh;
                        *(__half2*)(g_khf + ko) = __floats2half2_rn(a, b2);
                    }
                }
            }
        }
    }
}

// ---------------- attention (fp16, register-resident P, 2 blocks/SM) --------
// 8 warps x m16 q-rows; S = m16 x n128 per warp (P warp-private in regs);
// PV consumes S accum fragments directly as A-operands. One barrier per iter.
// smem: Q 16K @0 | 3 stages x 32K {K 16K, V 16K} @16384 = 112KB -> 2 blocks/SM
#define A_Q  0
#define A_ST 16384
#define A_STAGE 32768
#define A_SMEM (16384 + 3*32768)     // 114688 (112KB)

__global__ void __launch_bounds__(256, 2) attn_tc(const float* __restrict__ mask){
    extern __shared__ char sm[];
    uint32_t sb = smem_u32(sm);
    const int tid = threadIdx.x, wid = tid >> 5, lane = tid & 31;
    const int q0 = blockIdx.x * 128, h = blockIdx.y, b = blockIdx.z;
    const size_t bh = (size_t)b * HH + h;
    const int R0 = wid * 16;

    const __half* Qf = g_qhf + (bh*TQ + q0)*64;
    const __half* Kf = g_khf + bh * (size_t)TKV * 64;
    const __half* Vf = g_vt  + bh * (size_t)64 * TKV;

    // Q (persistent)
#pragma unroll
    for (int i = 0; i < 4; i++){
        int f = i*256 + tid, r = f >> 3, kc = f & 7;
        cp16(sb + A_Q + SW128((uint32_t)(r*128 + kc*16)), Qf + f*8);
    }
    CP_COMMIT();

#define A_ISSUE(it) do { \
    int kv0_ = (it) * 128; \
    uint32_t base_ = sb + A_ST + ((it) % 3) * A_STAGE; \
    _Pragma("unroll") \
    for (int i_ = 0; i_ < 4; i_++){ \
        int f_ = i_*256 + tid; \
        int r_ = f_ >> 3, kc_ = f_ & 7; \
        cp16(base_ + SW128((uint32_t)(r_*128 + kc_*16)), Kf + (size_t)kv0_*64 + f_*8); \
        int r2_ = f_ >> 4, kc2_ = f_ & 15; \
        uint32_t d2_ = (uint32_t)(r2_*256 + ((kc2_ >> 3) << 7) + (((kc2_ & 7) ^ (r2_ & 7)) << 4)); \
        cp16(base_ + 16384 + d2_, Vf + (size_t)r2_*TKV + kv0_ + kc2_*8); \
    } \
    CP_COMMIT(); \
} while (0)

    A_ISSUE(0);
    A_ISSUE(1);

    float Oacc[8][4];
#pragma unroll
    for (int i = 0; i < 8; i++)
#pragma unroll
        for (int j = 0; j < 4; j++) Oacc[i][j] = 0.f;
    float rs0 = 0.f, rs1 = 0.f;

    const int ar  = lane & 15;
    const int akh = lane >> 4;
    const int bi  = lane & 7;
    const int grp = lane >> 3;
    const float* m1 = mask + (size_t)(q0 + R0 + (lane >> 2))*TKV + (lane & 3)*2;
    const float* m2 = m1 + 8*TKV;

    uint32_t qf[4][4];   // Q fragments, loaded once at it==0

    for (int it = 0; it < 16; it++){
        int kv0 = it * 128;
        if (it < 15) asm volatile("cp.async.wait_group 1;" ::: "memory");
        else         asm volatile("cp.async.wait_group 0;" ::: "memory");
        __syncthreads();
        uint32_t ba = sb + A_ST + (it % 3) * A_STAGE;

        if (it == 0){
#pragma unroll
            for (int k16 = 0; k16 < 4; k16++)
                ldm4(qf[k16], sb + A_Q + SW128((uint32_t)((R0 + ar)*128 + (k16*2 + akh)*16)));
        }

        // S = Q K^T, warp tile m16 x n128 in two n64 halves; exp + pack to regs
        uint32_t pkA[16], pkB[16];   // per n8-group: rows r / r+8 packed half2
#pragma unroll
        for (int h2 = 0; h2 < 2; h2++){
            float Sacc[8][4];
#pragma unroll
            for (int i = 0; i < 8; i++)
#pragma unroll
                for (int j = 0; j < 4; j++) Sacc[i][j] = 0.f;
#pragma unroll
            for (int k16 = 0; k16 < 4; k16++){
#pragma unroll
                for (int np = 0; np < 4; np++){
                    int bn  = h2*64 + np*16 + (grp >> 1)*8 + bi;
                    int bkc = k16*2 + (grp & 1);
                    uint32_t kf[4];
                    ldm4(kf, ba + SW128((uint32_t)(bn*128 + bkc*16)));
                    mma_f16(Sacc[np*2],   qf[k16], kf[0], kf[1]);
                    mma_f16(Sacc[np*2+1], qf[k16], kf[2], kf[3]);
                }
            }
#pragma unroll
            for (int nf = 0; nf < 8; nf++){
                int g = h2*8 + nf;
                const float* ma = m1 + kv0 + h2*64 + nf*8;
                const float* mb = m2 + kv0 + h2*64 + nf*8;
                float2 mav = *(const float2*)ma;
                float2 mbv = *(const float2*)mb;
                float p0 = __expf(Sacc[nf][0] + mav.x);
                float p1 = __expf(Sacc[nf][1] + mav.y);
                float p2 = __expf(Sacc[nf][2] + mbv.x);
                float p3 = __expf(Sacc[nf][3] + mbv.y);
                rs0 += p0 + p1; rs1 += p2 + p3;
                pkA[g] = h2u(__floats2half2_rn(p0, p1));
                pkB[g] = h2u(__floats2half2_rn(p2, p3));
            }
        }

        // O += P V^T: P fragments straight from registers
#pragma unroll
        for (int j = 0; j < 8; j++){
            uint32_t af[4] = { pkA[2*j], pkB[2*j], pkA[2*j + 1], pkB[2*j + 1] };
#pragma unroll
            for (int np = 0; np < 4; np++){
                int vn  = np*16 + (grp >> 1)*8 + bi;
                int vkc = j*2 + (grp & 1);
                uint32_t vf[4];
                ldm4(vf, ba + 16384 + (uint32_t)(vn*256 + ((vkc >> 3) << 7) + (((vkc & 7) ^ (vn & 7)) << 4)));
                mma_f16(Oacc[np*2],   af, vf[0], vf[1]);
                mma_f16(Oacc[np*2+1], af, vf[2], vf[3]);
            }
        }

        // prefetch stage it+2 (buffer free: all warps passed this iter's barrier)
        if (it < 14) A_ISSUE(it + 2);
    }
#undef A_ISSUE

    // row-sum reduce across the 4 lanes sharing each row
    rs0 += __shfl_xor_sync(0xffffffffu, rs0, 1);
    rs0 += __shfl_xor_sync(0xffffffffu, rs0, 2);
    rs1 += __shfl_xor_sync(0xffffffffu, rs1, 1);
    rs1 += __shfl_xor_sync(0xffffffffu, rs1, 2);
    float inv0 = 1.f / rs0, inv1 = 1.f / rs1;

    // normalize + write attention output fp16 (head-major cols of [m,1024])
    int r1 = R0 + (lane >> 2), r2 = r1 + 8;
    size_t base1 = ((size_t)(b*TQ + q0 + r1))*DD + h*64;
    size_t base2 = ((size_t)(b*TQ + q0 + r2))*DD + h*64;
#pragma unroll
    for (int nf = 0; nf < 8; nf++){
        int c = nf*8 + (lane & 3)*2;
        *(__half2*)(g_av + base1 + c) = __floats2half2_rn(Oacc[nf][0]*inv0, Oacc[nf][1]*inv0);
        *(__half2*)(g_av + base2 + c) = __floats2half2_rn(Oacc[nf][2]*inv1, Oacc[nf][3]*inv1);
    }
}

// ---------------- launch ----------------------------------------------------
extern "C" void kernel_launch(void* const* d_in, const int* in_sizes, int n_in,
                              void* d_out, int out_size) {
    const float* x       = (const float*)d_in[0];
    const float* k_cache = (const float*)d_in[1];
    const float* v_cache = (const float*)d_in[2];
    const float* mask    = (const float*)d_in[3];
    const float* Wq      = (const float*)d_in[4];
    const float* bq      = (const float*)d_in[5];
    const float* Wk      = (const float*)d_in[6];
    const float* Wv      = (const float*)d_in[7];
    const float* bv      = (const float*)d_in[8];
    const float* Wo      = (const float*)d_in[9];
    const float* bo      = (const float*)d_in[10];

    float* outp = (float*)d_out;
    float* kout = outp + (size_t)BB * TQ * DD;
    float* vout = kout + (size_t)BB * TKV * DD;

    static int attr_done = 0;
    if (!attr_done){
        cudaFuncSetAttribute(gemm_tc, cudaFuncAttributeMaxDynamicSharedMemorySize, G_SMEM);
        cudaFuncSetAttribute(attn_tc, cudaFuncAttributeMaxDynamicSharedMemorySize, A_SMEM);
        attr_done = 1;
    }

    // 1) old cache rows -> output (+ K fp16 operands for old rows)
    {
        int n4 = BB * TQ * DD / 4;
        copy_old_cache<<<(n4 + 255)/256, 256>>>(
            (const float4*)k_cache, (const float4*)v_cache,
            (float4*)kout, (float4*)vout);
    }
    // 2) conversions
    conv_x<<<(BB*TQ*DD/4 + 255)/256, 256>>>((const float4*)x, BB*TQ*DD/4);
    conv_w4<<<dim3((DD*DD/4 + 255)/256, 4), 256>>>(
        (const float4*)Wq, (const float4*)Wk, (const float4*)Wv, (const float4*)Wo, DD*DD/4);
    // 3) QKV projections
    gemm_tc<<<dim3(DD/128, BB*TQ/128, 3), 256, G_SMEM>>>(0, bq, bv, bo, kout, vout, outp);
    // 4) V cache -> transposed fp16 operand
    vconv<<<dim3(TKV/128, HH, BB), 256>>>(vout);
    // 5) attention
    attn_tc<<<dim3(TQ/128, HH, BB), 256, A_SMEM>>>(mask);
    // 6) output projection
    gemm_tc<<<dim3(DD/128, BB*TQ/128, 1), 256, G_SMEM>>>(3, bq, bv, bo, kout, vout, outp);
}

// round 16
// speedup vs baseline: 2.1883x; 1.1445x over previous
#include <cuda_runtime.h>
#include <cuda_fp16.h>
#include <cstdint>
#include <math.h>

#define BB 4
#define TQ 1024
#define TKV 2048
#define DD 1024
#define HH 16
#define DHD 64

// ---------------- device scratch (static; no allocations) -------------------
__device__ __half g_x[BB*TQ*DD];                     // x fp16
__device__ __half g_Wq[DD*DD], g_Wk[DD*DD], g_Wv[DD*DD], g_Wo[DD*DD];
__device__ __half g_qhf[BB*TQ*DD];                   // [b,h,tq,64], x0.125
__device__ __half g_khf[BB*TKV*DD];                  // [b,h,kv,64]
__device__ __half g_vhf[BB*TKV*DD];                  // [b,h,kv,64] (natural layout)
__device__ __half g_av[BB*TQ*DD];                    // attn out fp16 [m,1024]
__device__ __half2 g_pm[TQ*1024];                    // mask packed fp16:
                                                     // [(q*16+kvt)*4+grp]*16 + g

// ---------------- helpers ---------------------------------------------------
__device__ __forceinline__ uint32_t smem_u32(const void* p){
    uint32_t a;
    asm("{ .reg .u64 t; cvta.to.shared.u64 t, %1; cvt.u32.u64 %0, t; }" : "=r"(a) : "l"(p));
    return a;
}
#define SW128(o) ((o) ^ (((o) >> 3) & 0x70))

__device__ __forceinline__ void ldm4(uint32_t* r, uint32_t addr){
    asm volatile("ldmatrix.sync.aligned.m8n8.x4.shared.b16 {%0,%1,%2,%3}, [%4];"
        : "=r"(r[0]), "=r"(r[1]), "=r"(r[2]), "=r"(r[3]) : "r"(addr));
}
__device__ __forceinline__ void ldm4t(uint32_t* r, uint32_t addr){
    asm volatile("ldmatrix.sync.aligned.m8n8.x4.trans.shared.b16 {%0,%1,%2,%3}, [%4];"
        : "=r"(r[0]), "=r"(r[1]), "=r"(r[2]), "=r"(r[3]) : "r"(addr));
}
__device__ __forceinline__ void mma_f16(float* c, const uint32_t* a, uint32_t b0, uint32_t b1){
    asm volatile("mma.sync.aligned.m16n8k16.row.col.f32.f16.f16.f32 "
        "{%0,%1,%2,%3}, {%4,%5,%6,%7}, {%8,%9}, {%0,%1,%2,%3};"
        : "+f"(c[0]), "+f"(c[1]), "+f"(c[2]), "+f"(c[3])
        : "r"(a[0]), "r"(a[1]), "r"(a[2]), "r"(a[3]), "r"(b0), "r"(b1));
}
__device__ __forceinline__ void cp16(uint32_t dst, const void* src){
    asm volatile("cp.async.cg.shared.global [%0], [%1], 16;" :: "r"(dst), "l"(src));
}
#define CP_COMMIT() asm volatile("cp.async.commit_group;")
__device__ __forceinline__ uint32_t h2u(__half2 v){
    return *reinterpret_cast<uint32_t*>(&v);
}

// ---------------- fused prep kernel -----------------------------------------
// grid (4096, 4), block 256; every segment is exactly 1M threads.
// seg 0: old cache rows -> output caches + K/V fp16 head-major operands
// seg 1: x fp32 -> fp16
// seg 2: weights fp32 -> fp16 (i>>18 selects Wq/Wk/Wv/Wo)
// seg 3: mask fp32 -> packed fp16 layout for attention fragment loads
__global__ void prep(const float4* __restrict__ x,
                     const float4* __restrict__ ksrc,
                     const float4* __restrict__ vsrc,
                     const float*  __restrict__ mask,
                     const float4* __restrict__ Wq, const float4* __restrict__ Wk,
                     const float4* __restrict__ Wv, const float4* __restrict__ Wo,
                     float4* __restrict__ kdst, float4* __restrict__ vdst){
    int i = blockIdx.x * blockDim.x + threadIdx.x;   // 0 .. 1M-1
    int seg = blockIdx.y;
    if (seg == 0){
        const int per_b = TQ * DD / 4;
        int b = i / per_b;
        int rem = i - b * per_b;
        size_t idx = (size_t)b * (TKV * DD / 4) + rem;
        float4 k4 = ksrc[idx], v4 = vsrc[idx];
        kdst[idx] = k4;
        vdst[idx] = v4;
        int t = rem >> 8;
        int d = (rem & 255) * 4;
        int h = d >> 6, dh = d & 63;
        size_t o = (((size_t)b*HH + h)*TKV + t)*64 + dh;
        *(__half2*)(g_khf + o)     = __floats2half2_rn(k4.x, k4.y);
        *(__half2*)(g_khf + o + 2) = __floats2half2_rn(k4.z, k4.w);
        *(__half2*)(g_vhf + o)     = __floats2half2_rn(v4.x, v4.y);
        *(__half2*)(g_vhf + o + 2) = __floats2half2_rn(v4.z, v4.w);
    } else if (seg == 1){
        float4 v = x[i];
        ((__half2*)g_x)[i*2+0] = __floats2half2_rn(v.x, v.y);
        ((__half2*)g_x)[i*2+1] = __floats2half2_rn(v.z, v.w);
    } else if (seg == 2){
        int which = i >> 18;
        int j = i & ((1 << 18) - 1);
        const float4* src;
        __half* W;
        switch (which){
            case 0: src = Wq; W = g_Wq; break;
            case 1: src = Wk; W = g_Wk; break;
            case 2: src = Wv; W = g_Wv; break;
            default:src = Wo; W = g_Wo; break;
        }
        float4 v = src[j];
        ((__half2*)W)[j*2+0] = __floats2half2_rn(v.x, v.y);
        ((__half2*)W)[j*2+1] = __floats2half2_rn(v.z, v.w);
    } else {
        // i = half2 index into g_pm: g = i&15, grp = (i>>4)&3, kvt = (i>>6)&15, q = i>>10
        int g = i & 15, grp = (i >> 4) & 3, kvt = (i >> 6) & 15, q = i >> 10;
        int col = kvt*128 + g*8 + grp*2;
        size_t mo = (size_t)q * TKV + col;
        g_pm[i] = __floats2half2_rn(mask[mo], mask[mo + 1]);
    }
}

// ---------------- fp16 1-pass projection GEMM (m32n64 warp tiles) -----------
#define G_STAGE 32768
#define G_SMEM  65536

__global__ void __launch_bounds__(256, 2) gemm_tc(int mode_base,
    const float* __restrict__ bq, const float* __restrict__ bvv, const float* __restrict__ bo,
    float* __restrict__ kout, float* __restrict__ vout, float* __restrict__ outp){
    extern __shared__ char sm[];
    const int mode = mode_base + blockIdx.z;
    const __half *A, *W;
    const float* bias;
    if (mode == 0)      { A=g_x;  W=g_Wq; bias=bq;  }
    else if (mode == 1) { A=g_x;  W=g_Wk; bias=0;   }
    else if (mode == 2) { A=g_x;  W=g_Wv; bias=bvv; }
    else                { A=g_av; W=g_Wo; bias=bo;  }

    uint32_t sb = smem_u32(sm);
    const int tid = threadIdx.x, wid = tid >> 5, lane = tid & 31;
    const int m0 = blockIdx.y * 128, n0 = blockIdx.x * 128;
    const int mg = wid & 3, ngr = wid >> 2;
    const int R0 = mg * 32, C0 = ngr * 64;

    const __half* srcs[2] = { A + (size_t)m0*DD, W + (size_t)n0*DD };
    const int lr = tid >> 3, lkc = tid & 7;

#define G_ISSUE(ch, buf) do { \
    int k0_ = (ch) * 64; \
    _Pragma("unroll") \
    for (int t2 = 0; t2 < 2; t2++){ \
        uint32_t base_ = sb + (buf)*G_STAGE + t2*16384; \
        _Pragma("unroll") \
        for (int i_ = 0; i_ < 4; i_++){ \
            int r_ = lr + i_*32; \
            cp16(base_ + SW128((uint32_t)(r_*128 + lkc*16)), \
                 srcs[t2] + (size_t)r_*DD + k0_ + lkc*8); \
        } \
    } \
    CP_COMMIT(); \
} while (0)

    G_ISSUE(0, 0);
    G_ISSUE(1, 1);

    float acc[16][4];
#pragma unroll
    for (int i = 0; i < 16; i++)
#pragma unroll
        for (int j = 0; j < 4; j++) acc[i][j] = 0.f;

    const int ar  = lane & 15;
    const int akh = lane >> 4;
    const int bi  = lane & 7;
    const int grp = lane >> 3;

    for (int ch = 0; ch < 16; ch++){
        if (ch == 15) asm volatile("cp.async.wait_group 0;" ::: "memory");
        else          asm volatile("cp.async.wait_group 1;" ::: "memory");
        __syncthreads();
        uint32_t ba = sb + (ch & 1) * G_STAGE;
#pragma unroll
        for (int k16 = 0; k16 < 4; k16++){
            uint32_t a0[4], a1[4];
            ldm4(a0, ba + SW128((uint32_t)((R0 + ar)*128      + (k16*2 + akh)*16)));
            ldm4(a1, ba + SW128((uint32_t)((R0 + 16 + ar)*128 + (k16*2 + akh)*16)));
#pragma unroll
            for (int np = 0; np < 4; np++){
                int bn  = C0 + np*16 + (grp >> 1)*8 + bi;
                int bkc = k16*2 + (grp & 1);
                uint32_t w[4];
                ldm4(w, ba + 16384 + SW128((uint32_t)(bn*128 + bkc*16)));
                mma_f16(acc[np*2],       a0, w[0], w[1]);
                mma_f16(acc[np*2+1],     a0, w[2], w[3]);
                mma_f16(acc[8 + np*2],   a1, w[0], w[1]);
                mma_f16(acc[8 + np*2+1], a1, w[2], w[3]);
            }
        }
        __syncthreads();
        if (ch + 2 < 16) G_ISSUE(ch + 2, ch & 1);
    }
#undef G_ISSUE

    // epilogue: warp covers rows m0+R0..+31, cols n0+C0..+63
#pragma unroll
    for (int i = 0; i < 2; i++){
        const int r1 = m0 + R0 + i*16 + (lane >> 2), r2 = r1 + 8;
#pragma unroll
        for (int nf = 0; nf < 8; nf++){
            int idx = i*8 + nf;
            int c = n0 + C0 + nf*8 + (lane & 3)*2;
            float v0 = acc[idx][0], v1 = acc[idx][1], v2 = acc[idx][2], v3 = acc[idx][3];
            if (bias){
                float2 bb = *(const float2*)(bias + c);
                v0 += bb.x; v1 += bb.y; v2 += bb.x; v3 += bb.y;
            }
            if (mode == 0){
                v0 *= 0.125f; v1 *= 0.125f; v2 *= 0.125f; v3 *= 0.125f;
                int h = c >> 6, dh = c & 63;
#pragma unroll
                for (int rr = 0; rr < 2; rr++){
                    int row = rr ? r2 : r1;
                    float a = rr ? v2 : v0, b2 = rr ? v3 : v1;
                    int b = row >> 10, q = row & 1023;
                    size_t o = (((size_t)b*HH + h)*TQ + q)*64 + dh;
                    *(__half2*)(g_qhf + o) = __floats2half2_rn(a, b2);
                }
            } else if (mode == 3){
                *(float2*)(outp + (size_t)r1*DD + c) = make_float2(v0, v1);
                *(float2*)(outp + (size_t)r2*DD + c) = make_float2(v2, v3);
            } else {
                float* dst  = (mode == 1) ? kout : vout;
                __half* gop = (mode == 1) ? g_khf : g_vhf;
                int h = c >> 6, dh = c & 63;
#pragma unroll
                for (int rr = 0; rr < 2; rr++){
                    int row = rr ? r2 : r1;
                    float a = rr ? v2 : v0, b2 = rr ? v3 : v1;
                    int b = row >> 10, q = row & 1023;
                    size_t o = ((size_t)b*TKV + TQ + q)*DD + c;
                    *(float2*)(dst + o) = make_float2(a, b2);
                    size_t ko = (((size_t)b*HH + h)*TKV + TQ + q)*64 + dh;
                    *(__half2*)(gop + ko) = __floats2half2_rn(a, b2);
                }
            }
        }
    }
}

// ---------------- attention (fp16, register P, trans-V, packed mask) --------
// 8 warps x m16 q-rows; S = m16 x n128 per warp; PV uses S accum fragments
// as A-operands and ldmatrix.trans V fragments. One barrier per iter.
// smem: Q 16K @0 | 3 stages x 32K {K 16K, V 16K} @16384 = 112KB -> 2 blocks/SM
#define A_Q  0
#define A_ST 16384
#define A_STAGE 32768
#define A_SMEM (16384 + 3*32768)     // 114688 (112KB)

__global__ void __launch_bounds__(256, 2) attn_tc(){
    extern __shared__ char sm[];
    uint32_t sb = smem_u32(sm);
    const int tid = threadIdx.x, wid = tid >> 5, lane = tid & 31;
    const int q0 = blockIdx.x * 128, h = blockIdx.y, b = blockIdx.z;
    const size_t bh = (size_t)b * HH + h;
    const int R0 = wid * 16;

    const __half* Qf = g_qhf + (bh*TQ + q0)*64;
    const __half* Kf = g_khf + bh * (size_t)TKV * 64;
    const __half* Vf = g_vhf + bh * (size_t)TKV * 64;

    // Q (persistent)
#pragma unroll
    for (int i = 0; i < 4; i++){
        int f = i*256 + tid, r = f >> 3, kc = f & 7;
        cp16(sb + A_Q + SW128((uint32_t)(r*128 + kc*16)), Qf + f*8);
    }
    CP_COMMIT();

#define A_ISSUE(it) do { \
    int kv0_ = (it) * 128; \
    uint32_t base_ = sb + A_ST + ((it) % 3) * A_STAGE; \
    _Pragma("unroll") \
    for (int i_ = 0; i_ < 4; i_++){ \
        int f_ = i_*256 + tid; \
        int r_ = f_ >> 3, kc_ = f_ & 7; \
        uint32_t d_ = SW128((uint32_t)(r_*128 + kc_*16)); \
        cp16(base_ + d_,         Kf + (size_t)(kv0_ + r_)*64 + kc_*8); \
        cp16(base_ + 16384 + d_, Vf + (size_t)(kv0_ + r_)*64 + kc_*8); \
    } \
    CP_COMMIT(); \
} while (0)

    A_ISSUE(0);
    A_ISSUE(1);

    float Oacc[8][4];
#pragma unroll
    for (int i = 0; i < 8; i++)
#pragma unroll
        for (int j = 0; j < 4; j++) Oacc[i][j] = 0.f;
    float rs0 = 0.f, rs1 = 0.f;

    const int ar  = lane & 15;
    const int akh = lane >> 4;
    const int bi  = lane & 7;
    const int grp = lane >> 3;

    // packed mask base for row r1 = q0+R0+(lane>>2); row2 = +8 -> +8*1024 half2
    const __half2* pmb = g_pm + (size_t)(q0 + R0 + (lane >> 2))*1024 + (lane & 3)*16;

    uint32_t qf[4][4];   // Q fragments, loaded once at it==0

    for (int it = 0; it < 16; it++){
        if (it < 15) asm volatile("cp.async.wait_group 1;" ::: "memory");
        else         asm volatile("cp.async.wait_group 0;" ::: "memory");
        __syncthreads();
        uint32_t ba = sb + A_ST + (it % 3) * A_STAGE;
        const __half2* pm1 = pmb + it*64;
        const __half2* pm2 = pm1 + 8*1024;

        if (it == 0){
#pragma unroll
            for (int k16 = 0; k16 < 4; k16++)
                ldm4(qf[k16], sb + A_Q + SW128((uint32_t)((R0 + ar)*128 + (k16*2 + akh)*16)));
        }

        // S = Q K^T, warp tile m16 x n128 in two n64 halves; exp + pack to regs
        uint32_t pkA[16], pkB[16];   // per n8-group: rows r / r+8 packed half2
#pragma unroll
        for (int h2 = 0; h2 < 2; h2++){
            float Sacc[8][4];
#pragma unroll
            for (int i = 0; i < 8; i++)
#pragma unroll
                for (int j = 0; j < 4; j++) Sacc[i][j] = 0.f;
#pragma unroll
            for (int k16 = 0; k16 < 4; k16++){
#pragma unroll
                for (int np = 0; np < 4; np++){
                    int bn  = h2*64 + np*16 + (grp >> 1)*8 + bi;
                    int bkc = k16*2 + (grp & 1);
                    uint32_t kf[4];
                    ldm4(kf, ba + SW128((uint32_t)(bn*128 + bkc*16)));
                    mma_f16(Sacc[np*2],   qf[k16], kf[0], kf[1]);
                    mma_f16(Sacc[np*2+1], qf[k16], kf[2], kf[3]);
                }
            }
            // packed fp16 mask: 8 half2 per row per half (2x uint4 loads each)
            __half2 mr1[8], mr2[8];
            *(uint4*)&mr1[0] = *(const uint4*)(pm1 + h2*8);
            *(uint4*)&mr1[4] = *(const uint4*)(pm1 + h2*8 + 4);
            *(uint4*)&mr2[0] = *(const uint4*)(pm2 + h2*8);
            *(uint4*)&mr2[4] = *(const uint4*)(pm2 + h2*8 + 4);
#pragma unroll
            for (int nf = 0; nf < 8; nf++){
                int g = h2*8 + nf;
                float2 mav = __half22float2(mr1[nf]);
                float2 mbv = __half22float2(mr2[nf]);
                float p0 = __expf(Sacc[nf][0] + mav.x);
                float p1 = __expf(Sacc[nf][1] + mav.y);
                float p2 = __expf(Sacc[nf][2] + mbv.x);
                float p3 = __expf(Sacc[nf][3] + mbv.y);
                rs0 += p0 + p1; rs1 += p2 + p3;
                pkA[g] = h2u(__floats2half2_rn(p0, p1));
                pkB[g] = h2u(__floats2half2_rn(p2, p3));
            }
        }

        // O += P V: P fragments from registers, V fragments via ldmatrix.trans
#pragma unroll
        for (int j = 0; j < 8; j++){
            uint32_t af[4] = { pkA[2*j], pkB[2*j], pkA[2*j + 1], pkB[2*j + 1] };
#pragma unroll
            for (int np = 0; np < 4; np++){
                int vr   = j*16 + (grp & 1)*8 + bi;     // kv row
                int vc16 = np*2 + (grp >> 1);           // 16B col chunk (dh)
                uint32_t vf[4];
                ldm4t(vf, ba + 16384 + SW128((uint32_t)(vr*128 + vc16*16)));
                mma_f16(Oacc[np*2],   af, vf[0], vf[1]);
                mma_f16(Oacc[np*2+1], af, vf[2], vf[3]);
            }
        }

        // prefetch stage it+2 (buffer free: all warps passed this iter's barrier)
        if (it < 14) A_ISSUE(it + 2);
    }
#undef A_ISSUE

    // row-sum reduce across the 4 lanes sharing each row
    rs0 += __shfl_xor_sync(0xffffffffu, rs0, 1);
    rs0 += __shfl_xor_sync(0xffffffffu, rs0, 2);
    rs1 += __shfl_xor_sync(0xffffffffu, rs1, 1);
    rs1 += __shfl_xor_sync(0xffffffffu, rs1, 2);
    float inv0 = 1.f / rs0, inv1 = 1.f / rs1;

    // normalize + write attention output fp16 (head-major cols of [m,1024])
    int r1 = R0 + (lane >> 2), r2 = r1 + 8;
    size_t base1 = ((size_t)(b*TQ + q0 + r1))*DD + h*64;
    size_t base2 = ((size_t)(b*TQ + q0 + r2))*DD + h*64;
#pragma unroll
    for (int nf = 0; nf < 8; nf++){
        int c = nf*8 + (lane & 3)*2;
        *(__half2*)(g_av + base1 + c) = __floats2half2_rn(Oacc[nf][0]*inv0, Oacc[nf][1]*inv0);
        *(__half2*)(g_av + base2 + c) = __floats2half2_rn(Oacc[nf][2]*inv1, Oacc[nf][3]*inv1);
    }
}

// ---------------- launch ----------------------------------------------------
extern "C" void kernel_launch(void* const* d_in, const int* in_sizes, int n_in,
                              void* d_out, int out_size) {
    const float* x       = (const float*)d_in[0];
    const float* k_cache = (const float*)d_in[1];
    const float* v_cache = (const float*)d_in[2];
    const float* mask    = (const float*)d_in[3];
    const float* Wq      = (const float*)d_in[4];
    const float* bq      = (const float*)d_in[5];
    const float* Wk      = (const float*)d_in[6];
    const float* Wv      = (const float*)d_in[7];
    const float* bv      = (const float*)d_in[8];
    const float* Wo      = (const float*)d_in[9];
    const float* bo      = (const float*)d_in[10];

    float* outp = (float*)d_out;
    float* kout = outp + (size_t)BB * TQ * DD;
    float* vout = kout + (size_t)BB * TKV * DD;

    static int attr_done = 0;
    if (!attr_done){
        cudaFuncSetAttribute(gemm_tc, cudaFuncAttributeMaxDynamicSharedMemorySize, G_SMEM);
        cudaFuncSetAttribute(attn_tc, cudaFuncAttributeMaxDynamicSharedMemorySize, A_SMEM);
        attr_done = 1;
    }

    // 1) fused prep: old-cache copy + all fp16 conversions + mask repack
    prep<<<dim3(4096, 4), 256>>>(
        (const float4*)x, (const float4*)k_cache, (const float4*)v_cache, mask,
        (const float4*)Wq, (const float4*)Wk, (const float4*)Wv, (const float4*)Wo,
        (float4*)kout, (float4*)vout);
    // 2) QKV projections (K/V fp16 operands fused in epilogues)
    gemm_tc<<<dim3(DD/128, BB*TQ/128, 3), 256, G_SMEM>>>(0, bq, bv, bo, kout, vout, outp);
    // 3) attention
    attn_tc<<<dim3(TQ/128, HH, BB), 256, A_SMEM>>>();
    // 4) output projection
    gemm_tc<<<dim3(DD/128, BB*TQ/128, 1), 256, G_SMEM>>>(3, bq, bv, bo, kout, vout, outp);
}

// round 17
// speedup vs baseline: 2.2091x; 1.0095x over previous
#include <cuda_runtime.h>
#include <cuda_fp16.h>
#include <cstdint>
#include <math.h>

#define BB 4
#define TQ 1024
#define TKV 2048
#define DD 1024
#define HH 16
#define DHD 64

#define QSCALE 0.18033688011112042f   // 0.125 * log2(e)
#define LOG2E  1.4426950408889634f

// ---------------- device scratch (static; no allocations) -------------------
__device__ __half g_x[BB*TQ*DD];                     // x fp16
__device__ __half g_Wq[DD*DD], g_Wk[DD*DD], g_Wv[DD*DD], g_Wo[DD*DD];
__device__ __half g_qhf[BB*TQ*DD];                   // [b,h,tq,64], x0.125*log2e
__device__ __half g_khf[BB*TKV*DD];                  // [b,h,kv,64]
__device__ __half g_vhf[BB*TKV*DD];                  // [b,h,kv,64] (natural layout)
__device__ __half g_av[BB*TQ*DD];                    // attn out fp16 [m,1024]
__device__ __half2 g_pm[TQ*1024];                    // mask*log2e packed fp16

// ---------------- helpers ---------------------------------------------------
__device__ __forceinline__ uint32_t smem_u32(const void* p){
    uint32_t a;
    asm("{ .reg .u64 t; cvta.to.shared.u64 t, %1; cvt.u32.u64 %0, t; }" : "=r"(a) : "l"(p));
    return a;
}
#define SW128(o) ((o) ^ (((o) >> 3) & 0x70))

__device__ __forceinline__ void ldm4(uint32_t* r, uint32_t addr){
    asm volatile("ldmatrix.sync.aligned.m8n8.x4.shared.b16 {%0,%1,%2,%3}, [%4];"
        : "=r"(r[0]), "=r"(r[1]), "=r"(r[2]), "=r"(r[3]) : "r"(addr));
}
__device__ __forceinline__ void ldm4t(uint32_t* r, uint32_t addr){
    asm volatile("ldmatrix.sync.aligned.m8n8.x4.trans.shared.b16 {%0,%1,%2,%3}, [%4];"
        : "=r"(r[0]), "=r"(r[1]), "=r"(r[2]), "=r"(r[3]) : "r"(addr));
}
__device__ __forceinline__ void mma_f16(float* c, const uint32_t* a, uint32_t b0, uint32_t b1){
    asm volatile("mma.sync.aligned.m16n8k16.row.col.f32.f16.f16.f32 "
        "{%0,%1,%2,%3}, {%4,%5,%6,%7}, {%8,%9}, {%0,%1,%2,%3};"
        : "+f"(c[0]), "+f"(c[1]), "+f"(c[2]), "+f"(c[3])
        : "r"(a[0]), "r"(a[1]), "r"(a[2]), "r"(a[3]), "r"(b0), "r"(b1));
}
__device__ __forceinline__ void cp16(uint32_t dst, const void* src){
    asm volatile("cp.async.cg.shared.global [%0], [%1], 16;" :: "r"(dst), "l"(src));
}
#define CP_COMMIT() asm volatile("cp.async.commit_group;")
__device__ __forceinline__ uint32_t h2u(__half2 v){
    return *reinterpret_cast<uint32_t*>(&v);
}

// ---------------- fused prep kernel -----------------------------------------
// grid (4096, 4), block 256; every segment is exactly 1M threads.
__global__ void prep(const float4* __restrict__ x,
                     const float4* __restrict__ ksrc,
                     const float4* __restrict__ vsrc,
                     const float*  __restrict__ mask,
                     const float4* __restrict__ Wq, const float4* __restrict__ Wk,
                     const float4* __restrict__ Wv, const float4* __restrict__ Wo,
                     float4* __restrict__ kdst, float4* __restrict__ vdst){
    int i = blockIdx.x * blockDim.x + threadIdx.x;   // 0 .. 1M-1
    int seg = blockIdx.y;
    if (seg == 0){
        const int per_b = TQ * DD / 4;
        int b = i / per_b;
        int rem = i - b * per_b;
        size_t idx = (size_t)b * (TKV * DD / 4) + rem;
        float4 k4 = ksrc[idx], v4 = vsrc[idx];
        kdst[idx] = k4;
        vdst[idx] = v4;
        int t = rem >> 8;
        int d = (rem & 255) * 4;
        int h = d >> 6, dh = d & 63;
        size_t o = (((size_t)b*HH + h)*TKV + t)*64 + dh;
        *(__half2*)(g_khf + o)     = __floats2half2_rn(k4.x, k4.y);
        *(__half2*)(g_khf + o + 2) = __floats2half2_rn(k4.z, k4.w);
        *(__half2*)(g_vhf + o)     = __floats2half2_rn(v4.x, v4.y);
        *(__half2*)(g_vhf + o + 2) = __floats2half2_rn(v4.z, v4.w);
    } else if (seg == 1){
        float4 v = x[i];
        ((__half2*)g_x)[i*2+0] = __floats2half2_rn(v.x, v.y);
        ((__half2*)g_x)[i*2+1] = __floats2half2_rn(v.z, v.w);
    } else if (seg == 2){
        int which = i >> 18;
        int j = i & ((1 << 18) - 1);
        const float4* src;
        __half* W;
        switch (which){
            case 0: src = Wq; W = g_Wq; break;
            case 1: src = Wk; W = g_Wk; break;
            case 2: src = Wv; W = g_Wv; break;
            default:src = Wo; W = g_Wo; break;
        }
        float4 v = src[j];
        ((__half2*)W)[j*2+0] = __floats2half2_rn(v.x, v.y);
        ((__half2*)W)[j*2+1] = __floats2half2_rn(v.z, v.w);
    } else {
        // mask * log2e, packed for fragment loads
        int g = i & 15, grp = (i >> 4) & 3, kvt = (i >> 6) & 15, q = i >> 10;
        int col = kvt*128 + g*8 + grp*2;
        size_t mo = (size_t)q * TKV + col;
        g_pm[i] = __floats2half2_rn(mask[mo]*LOG2E, mask[mo + 1]*LOG2E);
    }
}

// ---------------- fp16 1-pass projection GEMM (m32n64 warp tiles) -----------
// 3-stage cp.async ring, ONE barrier per K-chunk.
#define G_STAGE 32768
#define G_SMEM  (3*32768)    // 98304

__global__ void __launch_bounds__(256, 2) gemm_tc(int mode_base,
    const float* __restrict__ bq, const float* __restrict__ bvv, const float* __restrict__ bo,
    float* __restrict__ kout, float* __restrict__ vout, float* __restrict__ outp){
    extern __shared__ char sm[];
    const int mode = mode_base + blockIdx.z;
    const __half *A, *W;
    const float* bias;
    if (mode == 0)      { A=g_x;  W=g_Wq; bias=bq;  }
    else if (mode == 1) { A=g_x;  W=g_Wk; bias=0;   }
    else if (mode == 2) { A=g_x;  W=g_Wv; bias=bvv; }
    else                { A=g_av; W=g_Wo; bias=bo;  }

    uint32_t sb = smem_u32(sm);
    const int tid = threadIdx.x, wid = tid >> 5, lane = tid & 31;
    const int m0 = blockIdx.y * 128, n0 = blockIdx.x * 128;
    const int mg = wid & 3, ngr = wid >> 2;
    const int R0 = mg * 32, C0 = ngr * 64;

    const __half* srcs[2] = { A + (size_t)m0*DD, W + (size_t)n0*DD };
    const int lr = tid >> 3, lkc = tid & 7;

#define G_ISSUE(ch) do { \
    int k0_ = (ch) * 64; \
    uint32_t sbase_ = sb + ((ch) % 3) * G_STAGE; \
    _Pragma("unroll") \
    for (int t2 = 0; t2 < 2; t2++){ \
        uint32_t base_ = sbase_ + t2*16384; \
        _Pragma("unroll") \
        for (int i_ = 0; i_ < 4; i_++){ \
            int r_ = lr + i_*32; \
            cp16(base_ + SW128((uint32_t)(r_*128 + lkc*16)), \
                 srcs[t2] + (size_t)r_*DD + k0_ + lkc*8); \
        } \
    } \
    CP_COMMIT(); \
} while (0)

    G_ISSUE(0);
    G_ISSUE(1);

    float acc[16][4];
#pragma unroll
    for (int i = 0; i < 16; i++)
#pragma unroll
        for (int j = 0; j < 4; j++) acc[i][j] = 0.f;

    const int ar  = lane & 15;
    const int akh = lane >> 4;
    const int bi  = lane & 7;
    const int grp = lane >> 3;

    for (int ch = 0; ch < 16; ch++){
        if (ch == 15) asm volatile("cp.async.wait_group 0;" ::: "memory");
        else          asm volatile("cp.async.wait_group 1;" ::: "memory");
        __syncthreads();
        uint32_t ba = sb + (ch % 3) * G_STAGE;
#pragma unroll
        for (int k16 = 0; k16 < 4; k16++){
            uint32_t a0[4], a1[4];
            ldm4(a0, ba + SW128((uint32_t)((R0 + ar)*128      + (k16*2 + akh)*16)));
            ldm4(a1, ba + SW128((uint32_t)((R0 + 16 + ar)*128 + (k16*2 + akh)*16)));
#pragma unroll
            for (int np = 0; np < 4; np++){
                int bn  = C0 + np*16 + (grp >> 1)*8 + bi;
                int bkc = k16*2 + (grp & 1);
                uint32_t w[4];
                ldm4(w, ba + 16384 + SW128((uint32_t)(bn*128 + bkc*16)));
                mma_f16(acc[np*2],       a0, w[0], w[1]);
                mma_f16(acc[np*2+1],     a0, w[2], w[3]);
                mma_f16(acc[8 + np*2],   a1, w[0], w[1]);
                mma_f16(acc[8 + np*2+1], a1, w[2], w[3]);
            }
        }
        // issue chunk ch+2 into stage (ch+2)%3 = (ch-1)%3: last read in iter
        // ch-1; the barrier above proves all warps passed that iteration.
        if (ch + 2 < 16) G_ISSUE(ch + 2);
    }
#undef G_ISSUE

    // epilogue: warp covers rows m0+R0..+31, cols n0+C0..+63
#pragma unroll
    for (int i = 0; i < 2; i++){
        const int r1 = m0 + R0 + i*16 + (lane >> 2), r2 = r1 + 8;
#pragma unroll
        for (int nf = 0; nf < 8; nf++){
            int idx = i*8 + nf;
            int c = n0 + C0 + nf*8 + (lane & 3)*2;
            float v0 = acc[idx][0], v1 = acc[idx][1], v2 = acc[idx][2], v3 = acc[idx][3];
            if (bias){
                float2 bb = *(const float2*)(bias + c);
                v0 += bb.x; v1 += bb.y; v2 += bb.x; v3 += bb.y;
            }
            if (mode == 0){
                v0 *= QSCALE; v1 *= QSCALE; v2 *= QSCALE; v3 *= QSCALE;
                int h = c >> 6, dh = c & 63;
#pragma unroll
                for (int rr = 0; rr < 2; rr++){
                    int row = rr ? r2 : r1;
                    float a = rr ? v2 : v0, b2 = rr ? v3 : v1;
                    int b = row >> 10, q = row & 1023;
                    size_t o = (((size_t)b*HH + h)*TQ + q)*64 + dh;
                    *(__half2*)(g_qhf + o) = __floats2half2_rn(a, b2);
                }
            } else if (mode == 3){
                *(float2*)(outp + (size_t)r1*DD + c) = make_float2(v0, v1);
                *(float2*)(outp + (size_t)r2*DD + c) = make_float2(v2, v3);
            } else {
                float* dst  = (mode == 1) ? kout : vout;
                __half* gop = (mode == 1) ? g_khf : g_vhf;
                int h = c >> 6, dh = c & 63;
#pragma unroll
                for (int rr = 0; rr < 2; rr++){
                    int row = rr ? r2 : r1;
                    float a = rr ? v2 : v0, b2 = rr ? v3 : v1;
                    int b = row >> 10, q = row & 1023;
                    size_t o = ((size_t)b*TKV + TQ + q)*DD + c;
                    *(float2*)(dst + o) = make_float2(a, b2);
                    size_t ko = (((size_t)b*HH + h)*TKV + TQ + q)*64 + dh;
                    *(__half2*)(gop + ko) = __floats2half2_rn(a, b2);
                }
            }
        }
    }
}

// ---------------- attention (fp16, register P, trans-V, exp2) ---------------
// smem: Q 16K @0 | 3 stages x 32K {K 16K, V 16K} @16384 = 112KB -> 2 blocks/SM
#define A_Q  0
#define A_ST 16384
#define A_STAGE 32768
#define A_SMEM (16384 + 3*32768)     // 114688 (112KB)

__global__ void __launch_bounds__(256, 2) attn_tc(){
    extern __shared__ char sm[];
    uint32_t sb = smem_u32(sm);
    const int tid = threadIdx.x, wid = tid >> 5, lane = tid & 31;
    const int q0 = blockIdx.x * 128, h = blockIdx.y, b = blockIdx.z;
    const size_t bh = (size_t)b * HH + h;
    const int R0 = wid * 16;

    const __half* Qf = g_qhf + (bh*TQ + q0)*64;
    const __half* Kf = g_khf + bh * (size_t)TKV * 64;
    const __half* Vf = g_vhf + bh * (size_t)TKV * 64;

    // Q (persistent)
#pragma unroll
    for (int i = 0; i < 4; i++){
        int f = i*256 + tid, r = f >> 3, kc = f & 7;
        cp16(sb + A_Q + SW128((uint32_t)(r*128 + kc*16)), Qf + f*8);
    }
    CP_COMMIT();

#define A_ISSUE(it) do { \
    int kv0_ = (it) * 128; \
    uint32_t base_ = sb + A_ST + ((it) % 3) * A_STAGE; \
    _Pragma("unroll") \
    for (int i_ = 0; i_ < 4; i_++){ \
        int f_ = i_*256 + tid; \
        int r_ = f_ >> 3, kc_ = f_ & 7; \
        uint32_t d_ = SW128((uint32_t)(r_*128 + kc_*16)); \
        cp16(base_ + d_,         Kf + (size_t)(kv0_ + r_)*64 + kc_*8); \
        cp16(base_ + 16384 + d_, Vf + (size_t)(kv0_ + r_)*64 + kc_*8); \
    } \
    CP_COMMIT(); \
} while (0)

    A_ISSUE(0);
    A_ISSUE(1);

    float Oacc[8][4];
#pragma unroll
    for (int i = 0; i < 8; i++)
#pragma unroll
        for (int j = 0; j < 4; j++) Oacc[i][j] = 0.f;
    float rs0 = 0.f, rs1 = 0.f;

    const int ar  = lane & 15;
    const int akh = lane >> 4;
    const int bi  = lane & 7;
    const int grp = lane >> 3;

    const __half2* pmb = g_pm + (size_t)(q0 + R0 + (lane >> 2))*1024 + (lane & 3)*16;

    uint32_t qf[4][4];

    for (int it = 0; it < 16; it++){
        if (it < 15) asm volatile("cp.async.wait_group 1;" ::: "memory");
        else         asm volatile("cp.async.wait_group 0;" ::: "memory");
        __syncthreads();
        uint32_t ba = sb + A_ST + (it % 3) * A_STAGE;
        const __half2* pm1 = pmb + it*64;
        const __half2* pm2 = pm1 + 8*1024;

        if (it == 0){
#pragma unroll
            for (int k16 = 0; k16 < 4; k16++)
                ldm4(qf[k16], sb + A_Q + SW128((uint32_t)((R0 + ar)*128 + (k16*2 + akh)*16)));
        }

        // S = Q K^T (scaled by log2e); exp2 + pack to regs
        uint32_t pkA[16], pkB[16];
#pragma unroll
        for (int h2 = 0; h2 < 2; h2++){
            float Sacc[8][4];
#pragma unroll
            for (int i = 0; i < 8; i++)
#pragma unroll
                for (int j = 0; j < 4; j++) Sacc[i][j] = 0.f;
#pragma unroll
            for (int k16 = 0; k16 < 4; k16++){
#pragma unroll
                for (int np = 0; np < 4; np++){
                    int bn  = h2*64 + np*16 + (grp >> 1)*8 + bi;
                    int bkc = k16*2 + (grp & 1);
                    uint32_t kf[4];
                    ldm4(kf, ba + SW128((uint32_t)(bn*128 + bkc*16)));
                    mma_f16(Sacc[np*2],   qf[k16], kf[0], kf[1]);
                    mma_f16(Sacc[np*2+1], qf[k16], kf[2], kf[3]);
                }
            }
            __half2 mr1[8], mr2[8];
            *(uint4*)&mr1[0] = *(const uint4*)(pm1 + h2*8);
            *(uint4*)&mr1[4] = *(const uint4*)(pm1 + h2*8 + 4);
            *(uint4*)&mr2[0] = *(const uint4*)(pm2 + h2*8);
            *(uint4*)&mr2[4] = *(const uint4*)(pm2 + h2*8 + 4);
#pragma unroll
            for (int nf = 0; nf < 8; nf++){
                int g = h2*8 + nf;
                float2 mav = __half22float2(mr1[nf]);
                float2 mbv = __half22float2(mr2[nf]);
                float p0 = exp2f(Sacc[nf][0] + mav.x);
                float p1 = exp2f(Sacc[nf][1] + mav.y);
                float p2 = exp2f(Sacc[nf][2] + mbv.x);
                float p3 = exp2f(Sacc[nf][3] + mbv.y);
                rs0 += p0 + p1; rs1 += p2 + p3;
                pkA[g] = h2u(__floats2half2_rn(p0, p1));
                pkB[g] = h2u(__floats2half2_rn(p2, p3));
            }
        }

        // O += P V: P fragments from registers, V via ldmatrix.trans
#pragma unroll
        for (int j = 0; j < 8; j++){
            uint32_t af[4] = { pkA[2*j], pkB[2*j], pkA[2*j + 1], pkB[2*j + 1] };
#pragma unroll
            for (int np = 0; np < 4; np++){
                int vr   = j*16 + (grp & 1)*8 + bi;
                int vc16 = np*2 + (grp >> 1);
                uint32_t vf[4];
                ldm4t(vf, ba + 16384 + SW128((uint32_t)(vr*128 + vc16*16)));
                mma_f16(Oacc[np*2],   af, vf[0], vf[1]);
                mma_f16(Oacc[np*2+1], af, vf[2], vf[3]);
            }
        }

        if (it < 14) A_ISSUE(it + 2);
    }
#undef A_ISSUE

    rs0 += __shfl_xor_sync(0xffffffffu, rs0, 1);
    rs0 += __shfl_xor_sync(0xffffffffu, rs0, 2);
    rs1 += __shfl_xor_sync(0xffffffffu, rs1, 1);
    rs1 += __shfl_xor_sync(0xffffffffu, rs1, 2);
    float inv0 = 1.f / rs0, inv1 = 1.f / rs1;

    int r1 = R0 + (lane >> 2), r2 = r1 + 8;
    size_t base1 = ((size_t)(b*TQ + q0 + r1))*DD + h*64;
    size_t base2 = ((size_t)(b*TQ + q0 + r2))*DD + h*64;
#pragma unroll
    for (int nf = 0; nf < 8; nf++){
        int c = nf*8 + (lane & 3)*2;
        *(__half2*)(g_av + base1 + c) = __floats2half2_rn(Oacc[nf][0]*inv0, Oacc[nf][1]*inv0);
        *(__half2*)(g_av + base2 + c) = __floats2half2_rn(Oacc[nf][2]*inv1, Oacc[nf][3]*inv1);
    }
}

// ---------------- launch ----------------------------------------------------
extern "C" void kernel_launch(void* const* d_in, const int* in_sizes, int n_in,
                              void* d_out, int out_size) {
    const float* x       = (const float*)d_in[0];
    const float* k_cache = (const float*)d_in[1];
    const float* v_cache = (const float*)d_in[2];
    const float* mask    = (const float*)d_in[3];
    const float* Wq      = (const float*)d_in[4];
    const float* bq      = (const float*)d_in[5];
    const float* Wk      = (const float*)d_in[6];
    const float* Wv      = (const float*)d_in[7];
    const float* bv      = (const float*)d_in[8];
    const float* Wo      = (const float*)d_in[9];
    const float* bo      = (const float*)d_in[10];

    float* outp = (float*)d_out;
    float* kout = outp + (size_t)BB * TQ * DD;
    float* vout = kout + (size_t)BB * TKV * DD;

    static int attr_done = 0;
    if (!attr_done){
        cudaFuncSetAttribute(gemm_tc, cudaFuncAttributeMaxDynamicSharedMemorySize, G_SMEM);
        cudaFuncSetAttribute(attn_tc, cudaFuncAttributeMaxDynamicSharedMemorySize, A_SMEM);
        attr_done = 1;
    }

    // 1) fused prep
    prep<<<dim3(4096, 4), 256>>>(
        (const float4*)x, (const float4*)k_cache, (const float4*)v_cache, mask,
        (const float4*)Wq, (const float4*)Wk, (const float4*)Wv, (const float4*)Wo,
        (float4*)kout, (float4*)vout);
    // 2) QKV projections
    gemm_tc<<<dim3(DD/128, BB*TQ/128, 3), 256, G_SMEM>>>(0, bq, bv, bo, kout, vout, outp);
    // 3) attention
    attn_tc<<<dim3(TQ/128, HH, BB), 256, A_SMEM>>>();
    // 4) output projection
    gemm_tc<<<dim3(DD/128, BB*TQ/128, 1), 256, G_SMEM>>>(3, bq, bv, bo, kout, vout, outp);
}